// round 8
// baseline (speedup 1.0000x reference)
#include <cuda_runtime.h>
#include <cuda_bf16.h>
#include <math.h>
#include <stdint.h>

// EntityLinker via bf16 split-precision mma.sync (HMMA fallback, base sm_103).
//
// Round-8: algebraic work reduction.
//   P0 = node @ W1[0:128,:], P1 = node @ W1[128:256,:] precomputed PER NODE
//   (50k rows) by a tensor GEMM instead of per edge endpoint (1M).
//   Main kernel layer-1 only does the nonlinear segs (|diff|, prod):
//   HMMA per warp 1920 -> 1152. Epilogue-1 adds P0[src]+P1[dst] into the
//   accumulators (fp32 gather from L2-resident tables).
//
// Precision: x = x_hi(bf16) + x_lo(bf16 residual); 3 MMA terms
// (Ah@Bh + Al@Bh + Ah@Bl), fp32 accumulate; all paths still 3-term.

#define THREADS 512
#define MTILE 128
#define MAXN 50176          // capacity for node count (dataset: 50000)

// smem layout (bytes)
#define RS_A   272u          // 128 bf16 + 8 pad (LDSM conflict-free)
#define S0H    0u            // diff A hi [128 x 128] bf16
#define S0L    34816u        // diff A lo
#define S1H    69632u        // prod A hi
#define S1L    104448u       // prod A lo
#define RS_X   528u          // 256 bf16 + 8 pad
#define X_HI   0u            // layer2 A hi [128 x 256] (aliases S0, dead)
#define X_LO   69632u        // layer2 A lo (aliases S1)
#define IDX_OFF 139264u
#define SMEM_BYTES 140288
#define SMEM_PRE   69632     // precompute kernel: A tiles only

// packed weights: W1 4seg x 8ks x 2wn x 16nt x 2part x 32lane x 8B = 512KB
//                 W2 16ks x 2wn x 8nt x 2part x 32lane x 8B = 128KB
__device__ __align__(256) unsigned char g_w1p[524288];
__device__ __align__(256) unsigned char g_w2p[131072];
// per-node linear-segment outputs, fp32 [node][256]
__device__ float g_P0[(size_t)MAXN * 256];
__device__ float g_P1[(size_t)MAXN * 256];

// ---------------- helpers ----------------

__device__ __forceinline__ uint32_t smem_u32(const void* p) {
    uint32_t a;
    asm("{ .reg .u64 t; cvta.to.shared.u64 t, %1; cvt.u32.u64 %0, t; }"
        : "=r"(a) : "l"(p));
    return a;
}

__device__ __forceinline__ void split2(float a, float b, uint32_t& h, uint32_t& l) {
    __nv_bfloat162 hh = __floats2bfloat162_rn(a, b);
    h = *reinterpret_cast<uint32_t*>(&hh);
    __nv_bfloat162 ll = __floats2bfloat162_rn(a - __bfloat162float(hh.x),
                                              b - __bfloat162float(hh.y));
    l = *reinterpret_cast<uint32_t*>(&ll);
}

__device__ __forceinline__ void ldsm4(uint32_t* r, uint32_t addr) {
    asm volatile("ldmatrix.sync.aligned.m8n8.x4.shared.b16 {%0,%1,%2,%3}, [%4];"
                 : "=r"(r[0]), "=r"(r[1]), "=r"(r[2]), "=r"(r[3]) : "r"(addr));
}

__device__ __forceinline__ void hmma(float* d, const uint32_t* a, uint2 b) {
    asm volatile(
        "mma.sync.aligned.m16n8k16.row.col.f32.bf16.bf16.f32 "
        "{%0,%1,%2,%3}, {%4,%5,%6,%7}, {%8,%9}, {%0,%1,%2,%3};"
        : "+f"(d[0]), "+f"(d[1]), "+f"(d[2]), "+f"(d[3])
        : "r"(a[0]), "r"(a[1]), "r"(a[2]), "r"(a[3]), "r"(b.x), "r"(b.y));
}

// ---------------- prep: pack W1/W2 fragment-major, bf16 hi/lo ----------------

__global__ void prep_weights(const float* __restrict__ W1,
                             const float* __restrict__ W2) {
    int t = blockIdx.x * blockDim.x + threadIdx.x;
    if (t < 65536) {
        int reg  = t & 1;
        int lane = (t >> 1) & 31;
        int site = t >> 6;
        int nt   = site & 15;
        int rest = site >> 4;           // (seg*8+ks)*2+wn
        int wn   = rest & 1;
        int ks   = (rest >> 1) & 7;
        int seg  = rest >> 4;
        int n  = wn * 128 + nt * 8 + (lane >> 2);
        int k0 = seg * 128 + ks * 16 + (lane & 3) * 2 + reg * 8;
        float w0 = W1[k0 * 256 + n];
        float w1 = W1[(k0 + 1) * 256 + n];
        uint32_t h, l;
        split2(w0, w1, h, l);
        size_t base = (size_t)site * 512 + lane * 8 + reg * 4;
        *(uint32_t*)(g_w1p + base)       = h;
        *(uint32_t*)(g_w1p + base + 256) = l;
    } else if (t < 65536 + 16384) {
        int u = t - 65536;
        int reg  = u & 1;
        int lane = (u >> 1) & 31;
        int site = u >> 6;              // (ks*2+wn)*8+nt
        int nt   = site & 7;
        int rest = site >> 3;
        int wn   = rest & 1;
        int ks   = rest >> 1;
        int n  = wn * 64 + nt * 8 + (lane >> 2);
        int k0 = ks * 16 + (lane & 3) * 2 + reg * 8;
        float w0 = W2[k0 * 128 + n];
        float w1 = W2[(k0 + 1) * 128 + n];
        uint32_t h, l;
        split2(w0, w1, h, l);
        size_t base = (size_t)site * 512 + lane * 8 + reg * 4;
        *(uint32_t*)(g_w2p + base)       = h;
        *(uint32_t*)(g_w2p + base + 256) = l;
    }
}

// ---------------- precompute: P0/P1 = node @ W1_seg{0,1} ----------------

__global__ void __launch_bounds__(THREADS, 1)
precompute_P_kernel(const float* __restrict__ node, int nn)
{
    extern __shared__ unsigned char smem[];
    const uint32_t sb = smem_u32(smem);
    const int tid = threadIdx.x;
    const int lid = tid & 31;
    const int wid = tid >> 5;
    const int wm  = wid & 7;
    const int wn  = wid >> 3;
    const int n0  = blockIdx.x * MTILE;

    // build A tiles (node rows, bf16 hi/lo)
    #pragma unroll
    for (int it = 0; it < 8; it++) {
        int m = it * 16 + wid;
        int row = n0 + m;
        if (row >= nn) row = nn - 1;
        float4 v = __ldg((const float4*)node + (size_t)row * 32 + lid);
        uint32_t h01, l01, h23, l23;
        split2(v.x, v.y, h01, l01);
        split2(v.z, v.w, h23, l23);
        uint32_t off = m * RS_A + lid * 8;
        *(uint2*)(smem + S0H + off) = make_uint2(h01, h23);
        *(uint2*)(smem + S0L + off) = make_uint2(l01, l23);
    }
    __syncthreads();

    #pragma unroll 1
    for (int p = 0; p < 2; p++) {
        float acc[16][4];
        #pragma unroll
        for (int nt = 0; nt < 16; nt++)
            #pragma unroll
            for (int j = 0; j < 4; j++) acc[nt][j] = 0.f;

        #pragma unroll 1
        for (int ks = 0; ks < 8; ks++) {
            uint32_t ah[4], al[4];
            uint32_t ab = sb + S0H + (wm * 16 + (lid & 15)) * RS_A
                        + ks * 32 + ((lid >> 4) << 4);
            ldsm4(ah, ab);
            ldsm4(al, ab + 34816);
            const unsigned char* bp =
                g_w1p + ((size_t)(((p << 3) + ks) * 2 + wn) << 13) + (lid << 3);
            #pragma unroll
            for (int np = 0; np < 8; np++) {
                uint2 bh0 = __ldg((const uint2*)(bp + (2 * np) * 512));
                uint2 bh1 = __ldg((const uint2*)(bp + (2 * np + 1) * 512));
                uint2 bl0 = __ldg((const uint2*)(bp + (2 * np) * 512 + 256));
                uint2 bl1 = __ldg((const uint2*)(bp + (2 * np + 1) * 512 + 256));
                hmma(acc[2 * np],     ah, bh0);
                hmma(acc[2 * np + 1], ah, bh1);
                hmma(acc[2 * np],     al, bh0);
                hmma(acc[2 * np + 1], al, bh1);
                hmma(acc[2 * np],     ah, bl0);
                hmma(acc[2 * np + 1], ah, bl1);
            }
        }

        float* P = p ? g_P1 : g_P0;
        int r0 = n0 + wm * 16 + (lid >> 2);
        #pragma unroll
        for (int nt = 0; nt < 16; nt++) {
            int c = wn * 128 + nt * 8 + (lid & 3) * 2;
            if (r0 < nn)
                *(float2*)(P + (size_t)r0 * 256 + c) = make_float2(acc[nt][0], acc[nt][1]);
            if (r0 + 8 < nn)
                *(float2*)(P + (size_t)(r0 + 8) * 256 + c) = make_float2(acc[nt][2], acc[nt][3]);
        }
    }
}

// ---------------- main kernel ----------------

__global__ void __launch_bounds__(THREADS, 1)
linker_hmma_kernel(const float* __restrict__ node,
                   const int* __restrict__ src, const int* __restrict__ dst,
                   const float* __restrict__ b1v, const float* __restrict__ b2v,
                   const float* __restrict__ W3, const float* __restrict__ b3,
                   float* __restrict__ out, int E)
{
    extern __shared__ unsigned char smem[];
    const uint32_t sb = smem_u32(smem);
    const int tid = threadIdx.x;
    const int lid = tid & 31;
    const int wid = tid >> 5;
    const int wm  = wid & 7;        // M-warp: rows 16*wm .. +15
    const int wn  = wid >> 3;       // N-warp (0/1)
    const int e0  = blockIdx.x * MTILE;

    // ---- edge indices ----
    int* s_idx = (int*)(smem + IDX_OFF);
    if (tid < 256) {
        int e = e0 + (tid & 127);
        int v = 0;
        if (e < E) v = (tid < 128) ? __ldg(src + e) : __ldg(dst + e);
        s_idx[tid] = v;
    }
    __syncthreads();

    // ---- gather h_i/h_j (fp32) -> build |diff| and prod tiles directly ----
    #pragma unroll
    for (int it = 0; it < 8; it++) {
        int m = it * 16 + wid;
        int rs = s_idx[m], rd = s_idx[128 + m];
        float4 vi = __ldg((const float4*)node + (size_t)rs * 32 + lid);
        float4 vj = __ldg((const float4*)node + (size_t)rd * 32 + lid);
        uint32_t off = m * RS_A + lid * 8;
        uint32_t h01, l01, h23, l23;
        split2(fabsf(vi.x - vj.x), fabsf(vi.y - vj.y), h01, l01);
        split2(fabsf(vi.z - vj.z), fabsf(vi.w - vj.w), h23, l23);
        *(uint2*)(smem + S0H + off) = make_uint2(h01, h23);
        *(uint2*)(smem + S0L + off) = make_uint2(l01, l23);
        split2(vi.x * vj.x, vi.y * vj.y, h01, l01);
        split2(vi.z * vj.z, vi.w * vj.w, h23, l23);
        *(uint2*)(smem + S1H + off) = make_uint2(h01, h23);
        *(uint2*)(smem + S1L + off) = make_uint2(l01, l23);
    }
    __syncthreads();

    // ================= layer 1 (segs 2,3 only) =================
    float acc[16][4];
    #pragma unroll
    for (int nt = 0; nt < 16; nt++)
        #pragma unroll
        for (int j = 0; j < 4; j++) acc[nt][j] = 0.f;

    #pragma unroll 1
    for (int sg = 0; sg < 2; sg++) {
        const uint32_t abase = sg ? S1H : S0H;   // sg0=|diff| (W1 seg2), sg1=prod (seg3)
        #pragma unroll 1
        for (int ks = 0; ks < 8; ks++) {
            uint32_t ah[4], al[4];
            uint32_t ab = sb + abase + (wm * 16 + (lid & 15)) * RS_A
                        + ks * 32 + ((lid >> 4) << 4);
            ldsm4(ah, ab);
            ldsm4(al, ab + 34816);

            const unsigned char* bp =
                g_w1p + ((size_t)((((sg + 2) << 3) + ks) * 2 + wn) << 13) + (lid << 3);
            #pragma unroll
            for (int np = 0; np < 8; np++) {
                uint2 bh0 = __ldg((const uint2*)(bp + (2 * np) * 512));
                uint2 bh1 = __ldg((const uint2*)(bp + (2 * np + 1) * 512));
                uint2 bl0 = __ldg((const uint2*)(bp + (2 * np) * 512 + 256));
                uint2 bl1 = __ldg((const uint2*)(bp + (2 * np + 1) * 512 + 256));
                hmma(acc[2 * np],     ah, bh0);
                hmma(acc[2 * np + 1], ah, bh1);
                hmma(acc[2 * np],     al, bh0);
                hmma(acc[2 * np + 1], al, bh1);
                hmma(acc[2 * np],     ah, bl0);
                hmma(acc[2 * np + 1], ah, bl1);
            }
        }
    }
    __syncthreads();   // ldsm of S0/S1 done before X overwrites them

    // ---- epilogue 1: + P0[src] + P1[dst] + b1, relu, split, store x1 ----
    {
        int r0 = wm * 16 + (lid >> 2);
        const float* p0a = g_P0 + (size_t)s_idx[r0] * 256;
        const float* p1a = g_P1 + (size_t)s_idx[128 + r0] * 256;
        const float* p0b = g_P0 + (size_t)s_idx[r0 + 8] * 256;
        const float* p1b = g_P1 + (size_t)s_idx[128 + r0 + 8] * 256;
        #pragma unroll
        for (int nt = 0; nt < 16; nt++) {
            int c = wn * 128 + nt * 8 + (lid & 3) * 2;
            float2 bb  = __ldg((const float2*)(b1v + c));
            float2 qa0 = __ldg((const float2*)(p0a + c));
            float2 qa1 = __ldg((const float2*)(p1a + c));
            float2 qb0 = __ldg((const float2*)(p0b + c));
            float2 qb1 = __ldg((const float2*)(p1b + c));
            float v0 = fmaxf(acc[nt][0] + bb.x + qa0.x + qa1.x, 0.f);
            float v1 = fmaxf(acc[nt][1] + bb.y + qa0.y + qa1.y, 0.f);
            float v2 = fmaxf(acc[nt][2] + bb.x + qb0.x + qb1.x, 0.f);
            float v3 = fmaxf(acc[nt][3] + bb.y + qb0.y + qb1.y, 0.f);
            uint32_t h, l;
            split2(v0, v1, h, l);
            *(uint32_t*)(smem + X_HI + r0 * RS_X + c * 2) = h;
            *(uint32_t*)(smem + X_LO + r0 * RS_X + c * 2) = l;
            split2(v2, v3, h, l);
            *(uint32_t*)(smem + X_HI + (r0 + 8) * RS_X + c * 2) = h;
            *(uint32_t*)(smem + X_LO + (r0 + 8) * RS_X + c * 2) = l;
        }
    }
    __syncthreads();

    // ================= layer 2 =================
    float acc2[8][4];
    #pragma unroll
    for (int nt = 0; nt < 8; nt++)
        #pragma unroll
        for (int j = 0; j < 4; j++) acc2[nt][j] = 0.f;

    #pragma unroll 1
    for (int ks = 0; ks < 16; ks++) {
        uint32_t ah[4], al[4];
        uint32_t ab = sb + X_HI + (wm * 16 + (lid & 15)) * RS_X
                    + ks * 32 + ((lid >> 4) << 4);
        ldsm4(ah, ab);
        ldsm4(al, ab + (X_LO - X_HI));

        const unsigned char* bp =
            g_w2p + ((size_t)(ks * 2 + wn) << 12) + (lid << 3);
        #pragma unroll
        for (int np = 0; np < 4; np++) {
            uint2 bh0 = __ldg((const uint2*)(bp + (2 * np) * 512));
            uint2 bh1 = __ldg((const uint2*)(bp + (2 * np + 1) * 512));
            uint2 bl0 = __ldg((const uint2*)(bp + (2 * np) * 512 + 256));
            uint2 bl1 = __ldg((const uint2*)(bp + (2 * np + 1) * 512 + 256));
            hmma(acc2[2 * np],     ah, bh0);
            hmma(acc2[2 * np + 1], ah, bh1);
            hmma(acc2[2 * np],     al, bh0);
            hmma(acc2[2 * np + 1], al, bh1);
            hmma(acc2[2 * np],     ah, bl0);
            hmma(acc2[2 * np + 1], ah, bl1);
        }
    }
    __syncthreads();   // X reads done before sred overwrites region

    // ---- epilogue 2: relu(+b2), @W3, reduce, +b3 ----
    float* sred = (float*)smem;    // [2 wn][128 rows][2 outs]
    {
        int r0 = wm * 16 + (lid >> 2);
        float s00 = 0.f, s01 = 0.f, s10 = 0.f, s11 = 0.f;
        #pragma unroll
        for (int nt = 0; nt < 8; nt++) {
            int c = wn * 64 + nt * 8 + (lid & 3) * 2;
            float bb0 = __ldg(b2v + c), bb1 = __ldg(b2v + c + 1);
            float x0 = fmaxf(acc2[nt][0] + bb0, 0.f);
            float x1 = fmaxf(acc2[nt][1] + bb1, 0.f);
            float x2 = fmaxf(acc2[nt][2] + bb0, 0.f);
            float x3 = fmaxf(acc2[nt][3] + bb1, 0.f);
            float w00 = __ldg(W3 + c * 2),       w01 = __ldg(W3 + c * 2 + 1);
            float w10 = __ldg(W3 + (c + 1) * 2), w11 = __ldg(W3 + (c + 1) * 2 + 1);
            s00 += x0 * w00 + x1 * w10;
            s01 += x0 * w01 + x1 * w11;
            s10 += x2 * w00 + x3 * w10;
            s11 += x2 * w01 + x3 * w11;
        }
        s00 += __shfl_xor_sync(0xffffffffu, s00, 1);
        s00 += __shfl_xor_sync(0xffffffffu, s00, 2);
        s01 += __shfl_xor_sync(0xffffffffu, s01, 1);
        s01 += __shfl_xor_sync(0xffffffffu, s01, 2);
        s10 += __shfl_xor_sync(0xffffffffu, s10, 1);
        s10 += __shfl_xor_sync(0xffffffffu, s10, 2);
        s11 += __shfl_xor_sync(0xffffffffu, s11, 1);
        s11 += __shfl_xor_sync(0xffffffffu, s11, 2);
        if ((lid & 3) == 0) {
            sred[(wn * 128 + r0) * 2 + 0] = s00;
            sred[(wn * 128 + r0) * 2 + 1] = s01;
            sred[(wn * 128 + r0 + 8) * 2 + 0] = s10;
            sred[(wn * 128 + r0 + 8) * 2 + 1] = s11;
        }
    }
    __syncthreads();

    if (tid < 128) {
        int e = e0 + tid;
        if (e < E) {
            out[2 * e + 0] = sred[tid * 2 + 0] + sred[(128 + tid) * 2 + 0] + __ldg(b3 + 0);
            out[2 * e + 1] = sred[tid * 2 + 1] + sred[(128 + tid) * 2 + 1] + __ldg(b3 + 1);
        }
    }
}

extern "C" void kernel_launch(void* const* d_in, const int* in_sizes, int n_in,
                              void* d_out, int out_size)
{
    const float* node = (const float*)d_in[0];
    const int*   src  = (const int*)  d_in[1];
    const int*   dst  = (const int*)  d_in[2];
    const float* W1   = (const float*)d_in[3];
    const float* b1   = (const float*)d_in[4];
    const float* W2   = (const float*)d_in[5];
    const float* b2   = (const float*)d_in[6];
    const float* W3   = (const float*)d_in[7];
    const float* b3   = (const float*)d_in[8];
    float* out = (float*)d_out;

    const int E  = in_sizes[1];
    int nn = in_sizes[0] / 128;
    if (nn > MAXN) nn = MAXN;

    prep_weights<<<320, 256>>>(W1, W2);

    cudaFuncSetAttribute(precompute_P_kernel,
                         cudaFuncAttributeMaxDynamicSharedMemorySize, SMEM_PRE);
    precompute_P_kernel<<<(nn + MTILE - 1) / MTILE, THREADS, SMEM_PRE>>>(node, nn);

    cudaFuncSetAttribute(linker_hmma_kernel,
                         cudaFuncAttributeMaxDynamicSharedMemorySize, SMEM_BYTES);
    const int grid = (E + MTILE - 1) / MTILE;
    linker_hmma_kernel<<<grid, THREADS, SMEM_BYTES>>>(
        node, src, dst, b1, b2, W3, b3, out, E);
}

// round 10
// speedup vs baseline: 1.0046x; 1.0046x over previous
#include <cuda_runtime.h>
#include <cuda_bf16.h>
#include <math.h>
#include <stdint.h>

// EntityLinker via bf16 split-precision mma.sync (HMMA fallback, base sm_103).
//
// Round-9 (from round-7 base, 1189us, tensor=65.7%):
//  - B operands staged per-CTA into smem via cp.async.cg double-buffer,
//    one step ahead; HMMA reads B with LDS.64. Removes the 8x redundant
//    per-warp B LDG streams and hides L2 latency behind compute.
//  - (Round-8 P-precompute reverted: 102MB P tables blew L2 -> regression.)
//
// Precision: x = x_hi(bf16) + x_lo(bf16 residual); 3 MMA terms
// (Ah@Bh + Al@Bh + Ah@Bl), fp32 accumulate inside mma.sync.

#define THREADS 512
#define MTILE 128

// smem layout (bytes)
#define RS_A   272u            // 128 bf16 + 8 pad (LDSM conflict-free)
#define S0H    0u              // seg0/2 A hi [128 x 128] bf16
#define S0L    34816u          // seg0/2 A lo
#define S1H    69632u          // seg1/3 A hi
#define S1L    104448u         // seg1/3 A lo
#define RS_X   528u            // 256 bf16 + 8 pad
#define X_HI   0u              // layer2 A hi [128 x 256] (aliases S0, dead)
#define X_LO   69632u          // layer2 A lo (aliases S1)
#define BB0    139264u         // B stage buffer 0 (16KB)
#define BB1    155648u         // B stage buffer 1 (16KB)
#define IDX_OFF 172032u
#define SMEM_BYTES 173056

// packed weights: W1 4seg x 8ks x 2wn x 16nt x 2part x 32lane x 8B = 512KB
//                 W2 16ks x 2wn x 8nt x 2part x 32lane x 8B = 128KB
__device__ __align__(256) unsigned char g_w1p[524288];
__device__ __align__(256) unsigned char g_w2p[131072];

// ---------------- helpers ----------------

__device__ __forceinline__ uint32_t smem_u32(const void* p) {
    uint32_t a;
    asm("{ .reg .u64 t; cvta.to.shared.u64 t, %1; cvt.u32.u64 %0, t; }"
        : "=r"(a) : "l"(p));
    return a;
}

__device__ __forceinline__ void split2(float a, float b, uint32_t& h, uint32_t& l) {
    __nv_bfloat162 hh = __floats2bfloat162_rn(a, b);
    h = *reinterpret_cast<uint32_t*>(&hh);
    __nv_bfloat162 ll = __floats2bfloat162_rn(a - __bfloat162float(hh.x),
                                              b - __bfloat162float(hh.y));
    l = *reinterpret_cast<uint32_t*>(&ll);
}

__device__ __forceinline__ void ldsm4(uint32_t* r, uint32_t addr) {
    asm volatile("ldmatrix.sync.aligned.m8n8.x4.shared.b16 {%0,%1,%2,%3}, [%4];"
                 : "=r"(r[0]), "=r"(r[1]), "=r"(r[2]), "=r"(r[3]) : "r"(addr));
}

__device__ __forceinline__ void hmma(float* d, const uint32_t* a, uint2 b) {
    asm volatile(
        "mma.sync.aligned.m16n8k16.row.col.f32.bf16.bf16.f32 "
        "{%0,%1,%2,%3}, {%4,%5,%6,%7}, {%8,%9}, {%0,%1,%2,%3};"
        : "+f"(d[0]), "+f"(d[1]), "+f"(d[2]), "+f"(d[3])
        : "r"(a[0]), "r"(a[1]), "r"(a[2]), "r"(a[3]), "r"(b.x), "r"(b.y));
}

__device__ __forceinline__ void cp16(uint32_t d, const void* s) {
    asm volatile("cp.async.cg.shared.global [%0], [%1], 16;"
                 :: "r"(d), "l"(s) : "memory");
}
__device__ __forceinline__ void cp_commit() {
    asm volatile("cp.async.commit_group;" ::: "memory");
}
template <int N>
__device__ __forceinline__ void cp_wait() {
    asm volatile("cp.async.wait_group %0;" :: "n"(N) : "memory");
}

// ---------------- prep: pack W1/W2 fragment-major, bf16 hi/lo ----------------

__global__ void prep_weights(const float* __restrict__ W1,
                             const float* __restrict__ W2) {
    int t = blockIdx.x * blockDim.x + threadIdx.x;
    if (t < 65536) {
        int reg  = t & 1;
        int lane = (t >> 1) & 31;
        int site = t >> 6;
        int nt   = site & 15;
        int rest = site >> 4;           // (seg*8+ks)*2+wn
        int wn   = rest & 1;
        int ks   = (rest >> 1) & 7;
        int seg  = rest >> 4;
        int n  = wn * 128 + nt * 8 + (lane >> 2);
        int k0 = seg * 128 + ks * 16 + (lane & 3) * 2 + reg * 8;
        float w0 = W1[k0 * 256 + n];
        float w1 = W1[(k0 + 1) * 256 + n];
        uint32_t h, l;
        split2(w0, w1, h, l);
        size_t base = (size_t)site * 512 + lane * 8 + reg * 4;
        *(uint32_t*)(g_w1p + base)       = h;
        *(uint32_t*)(g_w1p + base + 256) = l;
    } else if (t < 65536 + 16384) {
        int u = t - 65536;
        int reg  = u & 1;
        int lane = (u >> 1) & 31;
        int site = u >> 6;              // (ks*2+wn)*8+nt
        int nt   = site & 7;
        int rest = site >> 3;
        int wn   = rest & 1;
        int ks   = rest >> 1;
        int n  = wn * 64 + nt * 8 + (lane >> 2);
        int k0 = ks * 16 + (lane & 3) * 2 + reg * 8;
        float w0 = W2[k0 * 128 + n];
        float w1 = W2[(k0 + 1) * 128 + n];
        uint32_t h, l;
        split2(w0, w1, h, l);
        size_t base = (size_t)site * 512 + lane * 8 + reg * 4;
        *(uint32_t*)(g_w2p + base)       = h;
        *(uint32_t*)(g_w2p + base + 256) = l;
    }
}

// ---------------- main kernel ----------------

__global__ void __launch_bounds__(THREADS, 1)
linker_hmma_kernel(const float* __restrict__ node,
                   const int* __restrict__ src, const int* __restrict__ dst,
                   const float* __restrict__ b1v, const float* __restrict__ b2v,
                   const float* __restrict__ W3, const float* __restrict__ b3,
                   float* __restrict__ out, int E)
{
    extern __shared__ unsigned char smem[];
    const uint32_t sb = smem_u32(smem);
    const int tid = threadIdx.x;
    const int lid = tid & 31;
    const int wid = tid >> 5;
    const int wm  = wid & 7;        // M-warp: rows 16*wm .. +15
    const int wn  = wid >> 3;       // N-warp (0/1)
    const int e0  = blockIdx.x * MTILE;

    // ---- prologue: stage B steps 0 and 1 of layer 1 (overlaps the gather) ----
    {
        uint32_t o = (uint32_t)tid * 16;
        cp16(sb + BB0 + o, g_w1p + o);
        cp16(sb + BB0 + o + 8192, g_w1p + o + 8192);
        cp_commit();
        cp16(sb + BB1 + o, g_w1p + 16384 + o);
        cp16(sb + BB1 + o + 8192, g_w1p + 16384 + o + 8192);
        cp_commit();
    }

    // ---- edge indices ----
    int* s_idx = (int*)(smem + IDX_OFF);
    if (tid < 256) {
        int e = e0 + (tid & 127);
        int v = 0;
        if (e < E) v = (tid < 128) ? __ldg(src + e) : __ldg(dst + e);
        s_idx[tid] = v;
    }
    __syncthreads();

    // ---- gather + bf16-split straight into seg0/seg1 A tiles ----
    #pragma unroll
    for (int it = 0; it < 16; it++) {
        int lin = it * THREADS + tid;
        int m = lin >> 6, r = lin & 63;
        int isj = r >> 5, q = r & 31;
        int row = s_idx[isj * 128 + m];
        float4 v = __ldg((const float4*)node + (size_t)row * 32 + q);
        uint32_t h01, l01, h23, l23;
        split2(v.x, v.y, h01, l01);
        split2(v.z, v.w, h23, l23);
        uint32_t off = (isj ? S1H : S0H) + m * RS_A + q * 8;
        *(uint2*)(smem + off)         = make_uint2(h01, h23);
        *(uint2*)(smem + off + 34816) = make_uint2(l01, l23);
    }
    __syncthreads();

    // ================= layer 1 (pipelined B) =================
    float acc[16][4];
    #pragma unroll
    for (int nt = 0; nt < 16; nt++)
        #pragma unroll
        for (int j = 0; j < 4; j++) acc[nt][j] = 0.f;

    #pragma unroll 1
    for (int step = 0; step < 32; step++) {
        const int seg = step >> 3;
        const int ks  = step & 7;

        if (step == 16) {
            // in-place: S0 <- |h_i - h_j| (split), S1 <- h_i * h_j (split).
            // End-of-iter-15 barrier guarantees all ldsm reads done.
            #pragma unroll
            for (int it = 0; it < 16; it++) {
                int lin = it * THREADS + tid;
                int m = lin >> 6, c2 = lin & 63;
                uint32_t off = m * RS_A + c2 * 4;
                __nv_bfloat162 ih = *(__nv_bfloat162*)(smem + S0H + off);
                __nv_bfloat162 il = *(__nv_bfloat162*)(smem + S0L + off);
                __nv_bfloat162 jh = *(__nv_bfloat162*)(smem + S1H + off);
                __nv_bfloat162 jl = *(__nv_bfloat162*)(smem + S1L + off);
                float fi0 = __bfloat162float(ih.x) + __bfloat162float(il.x);
                float fi1 = __bfloat162float(ih.y) + __bfloat162float(il.y);
                float fj0 = __bfloat162float(jh.x) + __bfloat162float(jl.x);
                float fj1 = __bfloat162float(jh.y) + __bfloat162float(jl.y);
                uint32_t h, l;
                split2(fabsf(fi0 - fj0), fabsf(fi1 - fj1), h, l);
                *(uint32_t*)(smem + S0H + off) = h;
                *(uint32_t*)(smem + S0L + off) = l;
                split2(fi0 * fj0, fi1 * fj1, h, l);
                *(uint32_t*)(smem + S1H + off) = h;
                *(uint32_t*)(smem + S1L + off) = l;
            }
        }

        if (step < 31) cp_wait<1>(); else cp_wait<0>();
        __syncthreads();   // B[step] visible to all; transform (if any) visible

        const uint32_t bb = (step & 1) ? BB1 : BB0;
        const uint32_t abase = (seg & 1) ? S1H : S0H;

        uint32_t ah[4], al[4];
        uint32_t ab = sb + abase + (wm * 16 + (lid & 15)) * RS_A
                    + ks * 32 + ((lid >> 4) << 4);
        ldsm4(ah, ab);
        ldsm4(al, ab + 34816);

        const unsigned char* bp = smem + bb + wn * 8192 + (lid << 3);
        #pragma unroll
        for (int np = 0; np < 8; np++) {
            uint2 bh0 = *(const uint2*)(bp + (2 * np) * 512);
            uint2 bh1 = *(const uint2*)(bp + (2 * np + 1) * 512);
            uint2 bl0 = *(const uint2*)(bp + (2 * np) * 512 + 256);
            uint2 bl1 = *(const uint2*)(bp + (2 * np + 1) * 512 + 256);
            hmma(acc[2 * np],     ah, bh0);
            hmma(acc[2 * np + 1], ah, bh1);
            hmma(acc[2 * np],     al, bh0);
            hmma(acc[2 * np + 1], al, bh1);
            hmma(acc[2 * np],     ah, bl0);
            hmma(acc[2 * np + 1], ah, bl1);
        }
        __syncthreads();   // all reads of B[step] done -> buffer reusable

        if (step + 2 < 32) {
            uint32_t o = (uint32_t)tid * 16;
            size_t g = (size_t)(step + 2) * 16384;
            cp16(sb + bb + o, g_w1p + g + o);
            cp16(sb + bb + o + 8192, g_w1p + g + o + 8192);
            cp_commit();
        }
    }

    // ---- stage layer-2 B steps 0,1 (overlaps epilogue-1) ----
    {
        uint32_t o = (uint32_t)tid * 16;
        cp16(sb + BB0 + o, g_w2p + o);
        cp_commit();
        cp16(sb + BB1 + o, g_w2p + 8192 + o);
        cp_commit();
    }

    // ---- epilogue 1: relu(+b1), split, store x1 hi/lo ----
    {
        int r0 = wm * 16 + (lid >> 2);
        #pragma unroll
        for (int nt = 0; nt < 16; nt++) {
            int c = wn * 128 + nt * 8 + (lid & 3) * 2;
            float bb0 = __ldg(b1v + c), bb1 = __ldg(b1v + c + 1);
            float v0 = fmaxf(acc[nt][0] + bb0, 0.f);
            float v1 = fmaxf(acc[nt][1] + bb1, 0.f);
            float v2 = fmaxf(acc[nt][2] + bb0, 0.f);
            float v3 = fmaxf(acc[nt][3] + bb1, 0.f);
            uint32_t h, l;
            split2(v0, v1, h, l);
            *(uint32_t*)(smem + X_HI + r0 * RS_X + c * 2) = h;
            *(uint32_t*)(smem + X_LO + r0 * RS_X + c * 2) = l;
            split2(v2, v3, h, l);
            *(uint32_t*)(smem + X_HI + (r0 + 8) * RS_X + c * 2) = h;
            *(uint32_t*)(smem + X_LO + (r0 + 8) * RS_X + c * 2) = l;
        }
    }
    __syncthreads();

    // ================= layer 2 (pipelined B) =================
    float acc2[8][4];
    #pragma unroll
    for (int nt = 0; nt < 8; nt++)
        #pragma unroll
        for (int j = 0; j < 4; j++) acc2[nt][j] = 0.f;

    #pragma unroll 1
    for (int step = 0; step < 16; step++) {
        if (step < 15) cp_wait<1>(); else cp_wait<0>();
        __syncthreads();

        const uint32_t bb = (step & 1) ? BB1 : BB0;

        uint32_t ah[4], al[4];
        uint32_t ab = sb + X_HI + (wm * 16 + (lid & 15)) * RS_X
                    + step * 32 + ((lid >> 4) << 4);
        ldsm4(ah, ab);
        ldsm4(al, ab + (X_LO - X_HI));

        const unsigned char* bp = smem + bb + wn * 4096 + (lid << 3);
        #pragma unroll
        for (int np = 0; np < 4; np++) {
            uint2 bh0 = *(const uint2*)(bp + (2 * np) * 512);
            uint2 bh1 = *(const uint2*)(bp + (2 * np + 1) * 512);
            uint2 bl0 = *(const uint2*)(bp + (2 * np) * 512 + 256);
            uint2 bl1 = *(const uint2*)(bp + (2 * np + 1) * 512 + 256);
            hmma(acc2[2 * np],     ah, bh0);
            hmma(acc2[2 * np + 1], ah, bh1);
            hmma(acc2[2 * np],     al, bh0);
            hmma(acc2[2 * np + 1], al, bh1);
            hmma(acc2[2 * np],     ah, bl0);
            hmma(acc2[2 * np + 1], ah, bl1);
        }
        __syncthreads();

        if (step + 2 < 16) {
            uint32_t o = (uint32_t)tid * 16;
            cp16(sb + bb + o, g_w2p + (size_t)(step + 2) * 8192 + o);
            cp_commit();
        }
    }

    // ---- epilogue 2: relu(+b2), @W3, reduce, +b3 ----
    float* sred = (float*)smem;    // [2 wn][128 rows][2 outs] (X region dead)
    {
        int r0 = wm * 16 + (lid >> 2);
        float s00 = 0.f, s01 = 0.f, s10 = 0.f, s11 = 0.f;
        #pragma unroll
        for (int nt = 0; nt < 8; nt++) {
            int c = wn * 64 + nt * 8 + (lid & 3) * 2;
            float bb0 = __ldg(b2v + c), bb1 = __ldg(b2v + c + 1);
            float x0 = fmaxf(acc2[nt][0] + bb0, 0.f);
            float x1 = fmaxf(acc2[nt][1] + bb1, 0.f);
            float x2 = fmaxf(acc2[nt][2] + bb0, 0.f);
            float x3 = fmaxf(acc2[nt][3] + bb1, 0.f);
            float w00 = __ldg(W3 + c * 2),       w01 = __ldg(W3 + c * 2 + 1);
            float w10 = __ldg(W3 + (c + 1) * 2), w11 = __ldg(W3 + (c + 1) * 2 + 1);
            s00 += x0 * w00 + x1 * w10;
            s01 += x0 * w01 + x1 * w11;
            s10 += x2 * w00 + x3 * w10;
            s11 += x2 * w01 + x3 * w11;
        }
        s00 += __shfl_xor_sync(0xffffffffu, s00, 1);
        s00 += __shfl_xor_sync(0xffffffffu, s00, 2);
        s01 += __shfl_xor_sync(0xffffffffu, s01, 1);
        s01 += __shfl_xor_sync(0xffffffffu, s01, 2);
        s10 += __shfl_xor_sync(0xffffffffu, s10, 1);
        s10 += __shfl_xor_sync(0xffffffffu, s10, 2);
        s11 += __shfl_xor_sync(0xffffffffu, s11, 1);
        s11 += __shfl_xor_sync(0xffffffffu, s11, 2);
        if ((lid & 3) == 0) {
            sred[(wn * 128 + r0) * 2 + 0] = s00;
            sred[(wn * 128 + r0) * 2 + 1] = s01;
            sred[(wn * 128 + r0 + 8) * 2 + 0] = s10;
            sred[(wn * 128 + r0 + 8) * 2 + 1] = s11;
        }
    }
    __syncthreads();

    if (tid < 128) {
        int e = e0 + tid;
        if (e < E) {
            out[2 * e + 0] = sred[tid * 2 + 0] + sred[(128 + tid) * 2 + 0] + __ldg(b3 + 0);
            out[2 * e + 1] = sred[tid * 2 + 1] + sred[(128 + tid) * 2 + 1] + __ldg(b3 + 1);
        }
    }
}

extern "C" void kernel_launch(void* const* d_in, const int* in_sizes, int n_in,
                              void* d_out, int out_size)
{
    const float* node = (const float*)d_in[0];
    const int*   src  = (const int*)  d_in[1];
    const int*   dst  = (const int*)  d_in[2];
    const float* W1   = (const float*)d_in[3];
    const float* b1   = (const float*)d_in[4];
    const float* W2   = (const float*)d_in[5];
    const float* b2   = (const float*)d_in[6];
    const float* W3   = (const float*)d_in[7];
    const float* b3   = (const float*)d_in[8];
    float* out = (float*)d_out;

    const int E = in_sizes[1];

    prep_weights<<<320, 256>>>(W1, W2);

    cudaFuncSetAttribute(linker_hmma_kernel,
                         cudaFuncAttributeMaxDynamicSharedMemorySize, SMEM_BYTES);
    const int grid = (E + MTILE - 1) / MTILE;
    linker_hmma_kernel<<<grid, THREADS, SMEM_BYTES>>>(
        node, src, dst, b1, b2, W3, b3, out, E);
}

// round 11
// speedup vs baseline: 1.2191x; 1.2135x over previous
#include <cuda_runtime.h>
#include <cuda_bf16.h>
#include <math.h>
#include <stdint.h>

// EntityLinker via bf16 split-precision mma.sync (HMMA fallback, base sm_103).
//
// Round-11 (from round-7 base, 1189us/tensor 65.7%):
//  - MTILE 128 -> 64, THREADS 512 -> 256 (same 4Mx2N per-warp tiling, same
//    per-warp inner loops/regs). smem 140KB -> 70KB => 2 CTAs/SM: one CTA's
//    MMA stream overlaps the other's gather/transform/epilogue phases, and
//    barrier domains halve (8 warps).
//  - cp.async B staging reverted (round 9/10: +2 barriers/step lockstep-
//    coupled all warps -> tensor 57%, regression).
//
// Precision: x = x_hi(bf16) + x_lo(bf16 residual); 3 MMA terms
// (Ah@Bh + Al@Bh + Ah@Bl), fp32 accumulate inside mma.sync.

#define THREADS 256
#define MTILE 64

// smem layout (bytes)
#define RS_A   272u            // 128 bf16 + 8 pad (LDSM conflict-free)
#define A_TILE 17408u          // 64 rows * 272
#define S0H    0u              // seg0/2 A hi [64 x 128] bf16
#define S0L    17408u          // seg0/2 A lo
#define S1H    34816u          // seg1/3 A hi
#define S1L    52224u          // seg1/3 A lo
#define RS_X   528u            // 256 bf16 + 8 pad
#define X_HI   0u              // layer2 A hi [64 x 256] (aliases S0/S0L, dead)
#define X_LO   33792u          // layer2 A lo (aliases S1 region)
#define IDX_OFF 69632u
#define SMEM_BYTES 70144

// packed weights: W1 4seg x 8ks x 2wn x 16nt x 2part x 32lane x 8B = 512KB
//                 W2 16ks x 2wn x 8nt x 2part x 32lane x 8B = 128KB
__device__ __align__(256) unsigned char g_w1p[524288];
__device__ __align__(256) unsigned char g_w2p[131072];

// ---------------- helpers ----------------

__device__ __forceinline__ uint32_t smem_u32(const void* p) {
    uint32_t a;
    asm("{ .reg .u64 t; cvta.to.shared.u64 t, %1; cvt.u32.u64 %0, t; }"
        : "=r"(a) : "l"(p));
    return a;
}

__device__ __forceinline__ void split2(float a, float b, uint32_t& h, uint32_t& l) {
    __nv_bfloat162 hh = __floats2bfloat162_rn(a, b);
    h = *reinterpret_cast<uint32_t*>(&hh);
    __nv_bfloat162 ll = __floats2bfloat162_rn(a - __bfloat162float(hh.x),
                                              b - __bfloat162float(hh.y));
    l = *reinterpret_cast<uint32_t*>(&ll);
}

__device__ __forceinline__ void ldsm4(uint32_t* r, uint32_t addr) {
    asm volatile("ldmatrix.sync.aligned.m8n8.x4.shared.b16 {%0,%1,%2,%3}, [%4];"
                 : "=r"(r[0]), "=r"(r[1]), "=r"(r[2]), "=r"(r[3]) : "r"(addr));
}

__device__ __forceinline__ void hmma(float* d, const uint32_t* a, uint2 b) {
    asm volatile(
        "mma.sync.aligned.m16n8k16.row.col.f32.bf16.bf16.f32 "
        "{%0,%1,%2,%3}, {%4,%5,%6,%7}, {%8,%9}, {%0,%1,%2,%3};"
        : "+f"(d[0]), "+f"(d[1]), "+f"(d[2]), "+f"(d[3])
        : "r"(a[0]), "r"(a[1]), "r"(a[2]), "r"(a[3]), "r"(b.x), "r"(b.y));
}

// ---------------- prep: pack W1/W2 fragment-major, bf16 hi/lo ----------------

__global__ void prep_weights(const float* __restrict__ W1,
                             const float* __restrict__ W2) {
    int t = blockIdx.x * blockDim.x + threadIdx.x;
    if (t < 65536) {
        int reg  = t & 1;
        int lane = (t >> 1) & 31;
        int site = t >> 6;
        int nt   = site & 15;
        int rest = site >> 4;           // (seg*8+ks)*2+wn
        int wn   = rest & 1;
        int ks   = (rest >> 1) & 7;
        int seg  = rest >> 4;
        int n  = wn * 128 + nt * 8 + (lane >> 2);
        int k0 = seg * 128 + ks * 16 + (lane & 3) * 2 + reg * 8;
        float w0 = W1[k0 * 256 + n];
        float w1 = W1[(k0 + 1) * 256 + n];
        uint32_t h, l;
        split2(w0, w1, h, l);
        size_t base = (size_t)site * 512 + lane * 8 + reg * 4;
        *(uint32_t*)(g_w1p + base)       = h;
        *(uint32_t*)(g_w1p + base + 256) = l;
    } else if (t < 65536 + 16384) {
        int u = t - 65536;
        int reg  = u & 1;
        int lane = (u >> 1) & 31;
        int site = u >> 6;              // (ks*2+wn)*8+nt
        int nt   = site & 7;
        int rest = site >> 3;
        int wn   = rest & 1;
        int ks   = rest >> 1;
        int n  = wn * 64 + nt * 8 + (lane >> 2);
        int k0 = ks * 16 + (lane & 3) * 2 + reg * 8;
        float w0 = W2[k0 * 128 + n];
        float w1 = W2[(k0 + 1) * 128 + n];
        uint32_t h, l;
        split2(w0, w1, h, l);
        size_t base = (size_t)site * 512 + lane * 8 + reg * 4;
        *(uint32_t*)(g_w2p + base)       = h;
        *(uint32_t*)(g_w2p + base + 256) = l;
    }
}

// ---------------- main kernel ----------------

__global__ void __launch_bounds__(THREADS, 2)
linker_hmma_kernel(const float* __restrict__ node,
                   const int* __restrict__ src, const int* __restrict__ dst,
                   const float* __restrict__ b1v, const float* __restrict__ b2v,
                   const float* __restrict__ W3, const float* __restrict__ b3,
                   float* __restrict__ out, int E)
{
    extern __shared__ unsigned char smem[];
    const uint32_t sb = smem_u32(smem);
    const int tid = threadIdx.x;
    const int lid = tid & 31;
    const int wid = tid >> 5;
    const int wm  = wid & 3;        // M-warp: rows 16*wm .. +15
    const int wn  = wid >> 2;       // N-warp (0/1)
    const int e0  = blockIdx.x * MTILE;

    // ---- edge indices ----
    int* s_idx = (int*)(smem + IDX_OFF);
    if (tid < 128) {
        int e = e0 + (tid & 63);
        int v = 0;
        if (e < E) v = (tid < 64) ? __ldg(src + e) : __ldg(dst + e);
        s_idx[tid] = v;
    }
    __syncthreads();

    // ---- gather + bf16-split straight into seg0/seg1 A tiles ----
    #pragma unroll
    for (int it = 0; it < 16; it++) {
        int lin = it * THREADS + tid;
        int m = lin >> 6, r = lin & 63;
        int isj = r >> 5, q = r & 31;
        int row = s_idx[isj * 64 + m];
        float4 v = __ldg((const float4*)node + (size_t)row * 32 + q);
        uint32_t h01, l01, h23, l23;
        split2(v.x, v.y, h01, l01);
        split2(v.z, v.w, h23, l23);
        uint32_t off = (isj ? S1H : S0H) + m * RS_A + q * 8;
        *(uint2*)(smem + off)          = make_uint2(h01, h23);
        *(uint2*)(smem + off + A_TILE) = make_uint2(l01, l23);
    }
    __syncthreads();

    // ================= layer 1 =================
    float acc[16][4];
    #pragma unroll
    for (int nt = 0; nt < 16; nt++)
        #pragma unroll
        for (int j = 0; j < 4; j++) acc[nt][j] = 0.f;

    #pragma unroll 1
    for (int seg = 0; seg < 4; seg++) {
        if (seg == 2) {
            // in-place: S0 <- |h_i - h_j| (split), S1 <- h_i * h_j (split)
            __syncthreads();
            #pragma unroll
            for (int it = 0; it < 16; it++) {
                int lin = it * THREADS + tid;
                int m = lin >> 6, c2 = lin & 63;
                uint32_t off = m * RS_A + c2 * 4;
                __nv_bfloat162 ih = *(__nv_bfloat162*)(smem + S0H + off);
                __nv_bfloat162 il = *(__nv_bfloat162*)(smem + S0L + off);
                __nv_bfloat162 jh = *(__nv_bfloat162*)(smem + S1H + off);
                __nv_bfloat162 jl = *(__nv_bfloat162*)(smem + S1L + off);
                float fi0 = __bfloat162float(ih.x) + __bfloat162float(il.x);
                float fi1 = __bfloat162float(ih.y) + __bfloat162float(il.y);
                float fj0 = __bfloat162float(jh.x) + __bfloat162float(jl.x);
                float fj1 = __bfloat162float(jh.y) + __bfloat162float(jl.y);
                uint32_t h, l;
                split2(fabsf(fi0 - fj0), fabsf(fi1 - fj1), h, l);
                *(uint32_t*)(smem + S0H + off) = h;
                *(uint32_t*)(smem + S0L + off) = l;
                split2(fi0 * fj0, fi1 * fj1, h, l);
                *(uint32_t*)(smem + S1H + off) = h;
                *(uint32_t*)(smem + S1L + off) = l;
            }
            __syncthreads();
        }
        const uint32_t abase = (seg & 1) ? S1H : S0H;

        #pragma unroll 1
        for (int ks = 0; ks < 8; ks++) {
            uint32_t ah[4], al[4];
            uint32_t ab = sb + abase + (wm * 16 + (lid & 15)) * RS_A
                        + ks * 32 + ((lid >> 4) << 4);
            ldsm4(ah, ab);
            ldsm4(al, ab + A_TILE);

            const unsigned char* bp =
                g_w1p + ((size_t)(((seg << 3) + ks) * 2 + wn) << 13) + (lid << 3);
            #pragma unroll
            for (int np = 0; np < 8; np++) {
                uint2 bh0 = __ldg((const uint2*)(bp + (2 * np) * 512));
                uint2 bh1 = __ldg((const uint2*)(bp + (2 * np + 1) * 512));
                uint2 bl0 = __ldg((const uint2*)(bp + (2 * np) * 512 + 256));
                uint2 bl1 = __ldg((const uint2*)(bp + (2 * np + 1) * 512 + 256));
                hmma(acc[2 * np],     ah, bh0);
                hmma(acc[2 * np + 1], ah, bh1);
                hmma(acc[2 * np],     al, bh0);
                hmma(acc[2 * np + 1], al, bh1);
                hmma(acc[2 * np],     ah, bl0);
                hmma(acc[2 * np + 1], ah, bl1);
            }
        }
    }
    __syncthreads();   // all ldsm of S0/S1 done before X overwrites them

    // ---- epilogue 1: relu(+b1), split, store x1 hi/lo ----
    {
        int r0 = wm * 16 + (lid >> 2);
        #pragma unroll
        for (int nt = 0; nt < 16; nt++) {
            int c = wn * 128 + nt * 8 + (lid & 3) * 2;
            float bb0 = __ldg(b1v + c), bb1 = __ldg(b1v + c + 1);
            float v0 = fmaxf(acc[nt][0] + bb0, 0.f);
            float v1 = fmaxf(acc[nt][1] + bb1, 0.f);
            float v2 = fmaxf(acc[nt][2] + bb0, 0.f);
            float v3 = fmaxf(acc[nt][3] + bb1, 0.f);
            uint32_t h, l;
            split2(v0, v1, h, l);
            *(uint32_t*)(smem + X_HI + r0 * RS_X + c * 2) = h;
            *(uint32_t*)(smem + X_LO + r0 * RS_X + c * 2) = l;
            split2(v2, v3, h, l);
            *(uint32_t*)(smem + X_HI + (r0 + 8) * RS_X + c * 2) = h;
            *(uint32_t*)(smem + X_LO + (r0 + 8) * RS_X + c * 2) = l;
        }
    }
    __syncthreads();

    // ================= layer 2 =================
    float acc2[8][4];
    #pragma unroll
    for (int nt = 0; nt < 8; nt++)
        #pragma unroll
        for (int j = 0; j < 4; j++) acc2[nt][j] = 0.f;

    #pragma unroll 1
    for (int ks = 0; ks < 16; ks++) {
        uint32_t ah[4], al[4];
        uint32_t ab = sb + X_HI + (wm * 16 + (lid & 15)) * RS_X
                    + ks * 32 + ((lid >> 4) << 4);
        ldsm4(ah, ab);
        ldsm4(al, ab + (X_LO - X_HI));

        const unsigned char* bp =
            g_w2p + ((size_t)(ks * 2 + wn) << 12) + (lid << 3);
        #pragma unroll
        for (int np = 0; np < 4; np++) {
            uint2 bh0 = __ldg((const uint2*)(bp + (2 * np) * 512));
            uint2 bh1 = __ldg((const uint2*)(bp + (2 * np + 1) * 512));
            uint2 bl0 = __ldg((const uint2*)(bp + (2 * np) * 512 + 256));
            uint2 bl1 = __ldg((const uint2*)(bp + (2 * np + 1) * 512 + 256));
            hmma(acc2[2 * np],     ah, bh0);
            hmma(acc2[2 * np + 1], ah, bh1);
            hmma(acc2[2 * np],     al, bh0);
            hmma(acc2[2 * np + 1], al, bh1);
            hmma(acc2[2 * np],     ah, bl0);
            hmma(acc2[2 * np + 1], ah, bl1);
        }
    }
    __syncthreads();   // X reads done before sred overwrites region

    // ---- epilogue 2: relu(+b2), @W3, reduce, +b3 ----
    float* sred = (float*)smem;    // [2 wn][64 rows][2 outs]
    {
        int r0 = wm * 16 + (lid >> 2);
        float s00 = 0.f, s01 = 0.f, s10 = 0.f, s11 = 0.f;
        #pragma unroll
        for (int nt = 0; nt < 8; nt++) {
            int c = wn * 64 + nt * 8 + (lid & 3) * 2;
            float bb0 = __ldg(b2v + c), bb1 = __ldg(b2v + c + 1);
            float x0 = fmaxf(acc2[nt][0] + bb0, 0.f);
            float x1 = fmaxf(acc2[nt][1] + bb1, 0.f);
            float x2 = fmaxf(acc2[nt][2] + bb0, 0.f);
            float x3 = fmaxf(acc2[nt][3] + bb1, 0.f);
            float w00 = __ldg(W3 + c * 2),       w01 = __ldg(W3 + c * 2 + 1);
            float w10 = __ldg(W3 + (c + 1) * 2), w11 = __ldg(W3 + (c + 1) * 2 + 1);
            s00 += x0 * w00 + x1 * w10;
            s01 += x0 * w01 + x1 * w11;
            s10 += x2 * w00 + x3 * w10;
            s11 += x2 * w01 + x3 * w11;
        }
        s00 += __shfl_xor_sync(0xffffffffu, s00, 1);
        s00 += __shfl_xor_sync(0xffffffffu, s00, 2);
        s01 += __shfl_xor_sync(0xffffffffu, s01, 1);
        s01 += __shfl_xor_sync(0xffffffffu, s01, 2);
        s10 += __shfl_xor_sync(0xffffffffu, s10, 1);
        s10 += __shfl_xor_sync(0xffffffffu, s10, 2);
        s11 += __shfl_xor_sync(0xffffffffu, s11, 1);
        s11 += __shfl_xor_sync(0xffffffffu, s11, 2);
        if ((lid & 3) == 0) {
            sred[(wn * 64 + r0) * 2 + 0] = s00;
            sred[(wn * 64 + r0) * 2 + 1] = s01;
            sred[(wn * 64 + r0 + 8) * 2 + 0] = s10;
            sred[(wn * 64 + r0 + 8) * 2 + 1] = s11;
        }
    }
    __syncthreads();

    if (tid < 64) {
        int e = e0 + tid;
        if (e < E) {
            out[2 * e + 0] = sred[tid * 2 + 0] + sred[(64 + tid) * 2 + 0] + __ldg(b3 + 0);
            out[2 * e + 1] = sred[tid * 2 + 1] + sred[(64 + tid) * 2 + 1] + __ldg(b3 + 1);
        }
    }
}

extern "C" void kernel_launch(void* const* d_in, const int* in_sizes, int n_in,
                              void* d_out, int out_size)
{
    const float* node = (const float*)d_in[0];
    const int*   src  = (const int*)  d_in[1];
    const int*   dst  = (const int*)  d_in[2];
    const float* W1   = (const float*)d_in[3];
    const float* b1   = (const float*)d_in[4];
    const float* W2   = (const float*)d_in[5];
    const float* b2   = (const float*)d_in[6];
    const float* W3   = (const float*)d_in[7];
    const float* b3   = (const float*)d_in[8];
    float* out = (float*)d_out;

    const int E = in_sizes[1];

    prep_weights<<<320, 256>>>(W1, W2);

    cudaFuncSetAttribute(linker_hmma_kernel,
                         cudaFuncAttributeMaxDynamicSharedMemorySize, SMEM_BYTES);
    const int grid = (E + MTILE - 1) / MTILE;
    linker_hmma_kernel<<<grid, THREADS, SMEM_BYTES>>>(
        node, src, dst, b1, b2, W3, b3, out, E);
}

// round 12
// speedup vs baseline: 1.5855x; 1.3006x over previous
#include <cuda_runtime.h>
#include <cuda_bf16.h>
#include <cuda_fp16.h>
#include <math.h>
#include <stdint.h>

// EntityLinker via bf16 split-precision mma.sync (HMMA fallback, base sm_103).
//
// Round-12 (from round-11 base, 1149us / tensor 67.9%):
//  - Per-node precompute returns, L2-sized: P0 = node@W1[0:128],
//    P1 = node@W1[128:256] stored FP16 (51.4MB total; round-8's fp32 version
//    was 102MB and thrashed L2 -> regression). Working set ~81MB < L2.
//  - Main kernel layer-1 computes only the nonlinear segs (|diff|, prod):
//    per-warp HMMA 1920 -> 1152. Epilogue-1 adds P0[src]+P1[dst] (half2
//    gathers from L2) into the accumulators.
//  - Keeps round-11 wins: MTILE=64 / 256 thr / 2 CTAs/SM phase overlap.
//
// Precision: x = x_hi(bf16) + x_lo(bf16 residual); 3 MMA terms
// (Ah@Bh + Al@Bh + Ah@Bl), fp32 accumulate inside mma.sync. P tables fp16.

#define THREADS 256
#define MTILE 64
#define MAXN 50176

// smem layout, main kernel (bytes)
#define RS_A   272u            // 128 bf16 + 8 pad (LDSM conflict-free)
#define A_TILE 17408u          // 64 rows * 272
#define S0H    0u              // |diff| A hi [64 x 128] bf16
#define S0L    17408u          // |diff| A lo
#define S1H    34816u          // prod A hi
#define S1L    52224u          // prod A lo
#define RS_X   528u            // 256 bf16 + 8 pad
#define X_HI   0u              // layer2 A hi [64 x 256] (aliases S tiles)
#define X_LO   33792u          // layer2 A lo
#define IDX_OFF 69632u
#define SMEM_BYTES 70144
#define SMEM_PRE   69632       // precompute kernel: 128-row A hi/lo tiles

// packed weights: W1 4seg x 8ks x 2wn x 16nt x 2part x 32lane x 8B = 512KB
//                 W2 16ks x 2wn x 8nt x 2part x 32lane x 8B = 128KB
__device__ __align__(256) unsigned char g_w1p[524288];
__device__ __align__(256) unsigned char g_w2p[131072];
// per-node linear-segment outputs, fp16 [node][256]
__device__ __align__(256) __half g_P0[(size_t)MAXN * 256];
__device__ __align__(256) __half g_P1[(size_t)MAXN * 256];

// ---------------- helpers ----------------

__device__ __forceinline__ uint32_t smem_u32(const void* p) {
    uint32_t a;
    asm("{ .reg .u64 t; cvta.to.shared.u64 t, %1; cvt.u32.u64 %0, t; }"
        : "=r"(a) : "l"(p));
    return a;
}

__device__ __forceinline__ void split2(float a, float b, uint32_t& h, uint32_t& l) {
    __nv_bfloat162 hh = __floats2bfloat162_rn(a, b);
    h = *reinterpret_cast<uint32_t*>(&hh);
    __nv_bfloat162 ll = __floats2bfloat162_rn(a - __bfloat162float(hh.x),
                                              b - __bfloat162float(hh.y));
    l = *reinterpret_cast<uint32_t*>(&ll);
}

__device__ __forceinline__ void ldsm4(uint32_t* r, uint32_t addr) {
    asm volatile("ldmatrix.sync.aligned.m8n8.x4.shared.b16 {%0,%1,%2,%3}, [%4];"
                 : "=r"(r[0]), "=r"(r[1]), "=r"(r[2]), "=r"(r[3]) : "r"(addr));
}

__device__ __forceinline__ void hmma(float* d, const uint32_t* a, uint2 b) {
    asm volatile(
        "mma.sync.aligned.m16n8k16.row.col.f32.bf16.bf16.f32 "
        "{%0,%1,%2,%3}, {%4,%5,%6,%7}, {%8,%9}, {%0,%1,%2,%3};"
        : "+f"(d[0]), "+f"(d[1]), "+f"(d[2]), "+f"(d[3])
        : "r"(a[0]), "r"(a[1]), "r"(a[2]), "r"(a[3]), "r"(b.x), "r"(b.y));
}

// ---------------- prep: pack W1/W2 fragment-major, bf16 hi/lo ----------------

__global__ void prep_weights(const float* __restrict__ W1,
                             const float* __restrict__ W2) {
    int t = blockIdx.x * blockDim.x + threadIdx.x;
    if (t < 65536) {
        int reg  = t & 1;
        int lane = (t >> 1) & 31;
        int site = t >> 6;
        int nt   = site & 15;
        int rest = site >> 4;           // (seg*8+ks)*2+wn
        int wn   = rest & 1;
        int ks   = (rest >> 1) & 7;
        int seg  = rest >> 4;
        int n  = wn * 128 + nt * 8 + (lane >> 2);
        int k0 = seg * 128 + ks * 16 + (lane & 3) * 2 + reg * 8;
        float w0 = W1[k0 * 256 + n];
        float w1 = W1[(k0 + 1) * 256 + n];
        uint32_t h, l;
        split2(w0, w1, h, l);
        size_t base = (size_t)site * 512 + lane * 8 + reg * 4;
        *(uint32_t*)(g_w1p + base)       = h;
        *(uint32_t*)(g_w1p + base + 256) = l;
    } else if (t < 65536 + 16384) {
        int u = t - 65536;
        int reg  = u & 1;
        int lane = (u >> 1) & 31;
        int site = u >> 6;              // (ks*2+wn)*8+nt
        int nt   = site & 7;
        int rest = site >> 3;
        int wn   = rest & 1;
        int ks   = rest >> 1;
        int n  = wn * 64 + nt * 8 + (lane >> 2);
        int k0 = ks * 16 + (lane & 3) * 2 + reg * 8;
        float w0 = W2[k0 * 128 + n];
        float w1 = W2[(k0 + 1) * 128 + n];
        uint32_t h, l;
        split2(w0, w1, h, l);
        size_t base = (size_t)site * 512 + lane * 8 + reg * 4;
        *(uint32_t*)(g_w2p + base)       = h;
        *(uint32_t*)(g_w2p + base + 256) = l;
    }
}

// ---------------- precompute: P0/P1 = node @ W1_seg{0,1}, fp16 out ----------------

__global__ void __launch_bounds__(512, 1)
precompute_P_kernel(const float* __restrict__ node, int nn)
{
    extern __shared__ unsigned char smem[];
    const uint32_t sb = smem_u32(smem);
    const int tid = threadIdx.x;
    const int lid = tid & 31;
    const int wid = tid >> 5;
    const int wm  = wid & 7;
    const int wn  = wid >> 3;
    const int n0  = blockIdx.x * 128;

    // build A tiles (node rows, bf16 hi/lo), 128 rows
    #pragma unroll
    for (int it = 0; it < 8; it++) {
        int m = it * 16 + wid;
        int row = n0 + m;
        if (row >= nn) row = nn - 1;
        float4 v = __ldg((const float4*)node + (size_t)row * 32 + lid);
        uint32_t h01, l01, h23, l23;
        split2(v.x, v.y, h01, l01);
        split2(v.z, v.w, h23, l23);
        uint32_t off = m * RS_A + lid * 8;
        *(uint2*)(smem + off)          = make_uint2(h01, h23);
        *(uint2*)(smem + off + 34816u) = make_uint2(l01, l23);
    }
    __syncthreads();

    #pragma unroll 1
    for (int p = 0; p < 2; p++) {
        float acc[16][4];
        #pragma unroll
        for (int nt = 0; nt < 16; nt++)
            #pragma unroll
            for (int j = 0; j < 4; j++) acc[nt][j] = 0.f;

        #pragma unroll 1
        for (int ks = 0; ks < 8; ks++) {
            uint32_t ah[4], al[4];
            uint32_t ab = sb + (wm * 16 + (lid & 15)) * RS_A
                        + ks * 32 + ((lid >> 4) << 4);
            ldsm4(ah, ab);
            ldsm4(al, ab + 34816u);
            const unsigned char* bp =
                g_w1p + ((size_t)(((p << 3) + ks) * 2 + wn) << 13) + (lid << 3);
            #pragma unroll
            for (int np = 0; np < 8; np++) {
                uint2 bh0 = __ldg((const uint2*)(bp + (2 * np) * 512));
                uint2 bh1 = __ldg((const uint2*)(bp + (2 * np + 1) * 512));
                uint2 bl0 = __ldg((const uint2*)(bp + (2 * np) * 512 + 256));
                uint2 bl1 = __ldg((const uint2*)(bp + (2 * np + 1) * 512 + 256));
                hmma(acc[2 * np],     ah, bh0);
                hmma(acc[2 * np + 1], ah, bh1);
                hmma(acc[2 * np],     al, bh0);
                hmma(acc[2 * np + 1], al, bh1);
                hmma(acc[2 * np],     ah, bl0);
                hmma(acc[2 * np + 1], ah, bl1);
            }
        }

        __half2* P = (__half2*)(p ? g_P1 : g_P0);
        int r0 = n0 + wm * 16 + (lid >> 2);
        #pragma unroll
        for (int nt = 0; nt < 16; nt++) {
            int c = wn * 128 + nt * 8 + (lid & 3) * 2;
            if (r0 < nn)
                P[(size_t)r0 * 128 + (c >> 1)] = __floats2half2_rn(acc[nt][0], acc[nt][1]);
            if (r0 + 8 < nn)
                P[(size_t)(r0 + 8) * 128 + (c >> 1)] = __floats2half2_rn(acc[nt][2], acc[nt][3]);
        }
    }
}

// ---------------- main kernel ----------------

__global__ void __launch_bounds__(THREADS, 2)
linker_hmma_kernel(const float* __restrict__ node,
                   const int* __restrict__ src, const int* __restrict__ dst,
                   const float* __restrict__ b1v, const float* __restrict__ b2v,
                   const float* __restrict__ W3, const float* __restrict__ b3,
                   float* __restrict__ out, int E)
{
    extern __shared__ unsigned char smem[];
    const uint32_t sb = smem_u32(smem);
    const int tid = threadIdx.x;
    const int lid = tid & 31;
    const int wid = tid >> 5;
    const int wm  = wid & 3;        // M-warp: rows 16*wm .. +15
    const int wn  = wid >> 2;       // N-warp (0/1)
    const int e0  = blockIdx.x * MTILE;

    // ---- edge indices ----
    int* s_idx = (int*)(smem + IDX_OFF);
    if (tid < 128) {
        int e = e0 + (tid & 63);
        int v = 0;
        if (e < E) v = (tid < 64) ? __ldg(src + e) : __ldg(dst + e);
        s_idx[tid] = v;
    }
    __syncthreads();

    // ---- gather h_i/h_j (fp32) -> build |diff| and prod tiles directly ----
    #pragma unroll
    for (int it = 0; it < 8; it++) {
        int lin = it * THREADS + tid;
        int m = lin >> 5, q = lin & 31;
        int rs = s_idx[m], rd = s_idx[64 + m];
        float4 vi = __ldg((const float4*)node + (size_t)rs * 32 + q);
        float4 vj = __ldg((const float4*)node + (size_t)rd * 32 + q);
        uint32_t off = m * RS_A + q * 8;
        uint32_t h01, l01, h23, l23;
        split2(fabsf(vi.x - vj.x), fabsf(vi.y - vj.y), h01, l01);
        split2(fabsf(vi.z - vj.z), fabsf(vi.w - vj.w), h23, l23);
        *(uint2*)(smem + S0H + off) = make_uint2(h01, h23);
        *(uint2*)(smem + S0L + off) = make_uint2(l01, l23);
        split2(vi.x * vj.x, vi.y * vj.y, h01, l01);
        split2(vi.z * vj.z, vi.w * vj.w, h23, l23);
        *(uint2*)(smem + S1H + off) = make_uint2(h01, h23);
        *(uint2*)(smem + S1L + off) = make_uint2(l01, l23);
    }
    __syncthreads();

    // ================= layer 1 (nonlinear segs only: W1 segs 2,3) =================
    float acc[16][4];
    #pragma unroll
    for (int nt = 0; nt < 16; nt++)
        #pragma unroll
        for (int j = 0; j < 4; j++) acc[nt][j] = 0.f;

    #pragma unroll 1
    for (int sg = 0; sg < 2; sg++) {
        const uint32_t abase = sg ? S1H : S0H;
        #pragma unroll 1
        for (int ks = 0; ks < 8; ks++) {
            uint32_t ah[4], al[4];
            uint32_t ab = sb + abase + (wm * 16 + (lid & 15)) * RS_A
                        + ks * 32 + ((lid >> 4) << 4);
            ldsm4(ah, ab);
            ldsm4(al, ab + A_TILE);

            const unsigned char* bp =
                g_w1p + ((size_t)((((sg + 2) << 3) + ks) * 2 + wn) << 13) + (lid << 3);
            #pragma unroll
            for (int np = 0; np < 8; np++) {
                uint2 bh0 = __ldg((const uint2*)(bp + (2 * np) * 512));
                uint2 bh1 = __ldg((const uint2*)(bp + (2 * np + 1) * 512));
                uint2 bl0 = __ldg((const uint2*)(bp + (2 * np) * 512 + 256));
                uint2 bl1 = __ldg((const uint2*)(bp + (2 * np + 1) * 512 + 256));
                hmma(acc[2 * np],     ah, bh0);
                hmma(acc[2 * np + 1], ah, bh1);
                hmma(acc[2 * np],     al, bh0);
                hmma(acc[2 * np + 1], al, bh1);
                hmma(acc[2 * np],     ah, bl0);
                hmma(acc[2 * np + 1], ah, bl1);
            }
        }
    }
    __syncthreads();   // all ldsm of S tiles done before X overwrites them

    // ---- epilogue 1: + P0[src] + P1[dst] + b1, relu, split, store x1 ----
    {
        int r0 = wm * 16 + (lid >> 2);
        const __half2* p0a = (const __half2*)g_P0 + (size_t)s_idx[r0] * 128;
        const __half2* p1a = (const __half2*)g_P1 + (size_t)s_idx[64 + r0] * 128;
        const __half2* p0b = (const __half2*)g_P0 + (size_t)s_idx[r0 + 8] * 128;
        const __half2* p1b = (const __half2*)g_P1 + (size_t)s_idx[64 + r0 + 8] * 128;
        #pragma unroll
        for (int nt = 0; nt < 16; nt++) {
            int c = wn * 128 + nt * 8 + (lid & 3) * 2;
            int c2 = c >> 1;
            float2 bb  = __ldg((const float2*)(b1v + c));
            float2 qa0 = __half22float2(__ldg(p0a + c2));
            float2 qa1 = __half22float2(__ldg(p1a + c2));
            float2 qb0 = __half22float2(__ldg(p0b + c2));
            float2 qb1 = __half22float2(__ldg(p1b + c2));
            float v0 = fmaxf(acc[nt][0] + bb.x + qa0.x + qa1.x, 0.f);
            float v1 = fmaxf(acc[nt][1] + bb.y + qa0.y + qa1.y, 0.f);
            float v2 = fmaxf(acc[nt][2] + bb.x + qb0.x + qb1.x, 0.f);
            float v3 = fmaxf(acc[nt][3] + bb.y + qb0.y + qb1.y, 0.f);
            uint32_t h, l;
            split2(v0, v1, h, l);
            *(uint32_t*)(smem + X_HI + r0 * RS_X + c * 2) = h;
            *(uint32_t*)(smem + X_LO + r0 * RS_X + c * 2) = l;
            split2(v2, v3, h, l);
            *(uint32_t*)(smem + X_HI + (r0 + 8) * RS_X + c * 2) = h;
            *(uint32_t*)(smem + X_LO + (r0 + 8) * RS_X + c * 2) = l;
        }
    }
    __syncthreads();

    // ================= layer 2 =================
    float acc2[8][4];
    #pragma unroll
    for (int nt = 0; nt < 8; nt++)
        #pragma unroll
        for (int j = 0; j < 4; j++) acc2[nt][j] = 0.f;

    #pragma unroll 1
    for (int ks = 0; ks < 16; ks++) {
        uint32_t ah[4], al[4];
        uint32_t ab = sb + X_HI + (wm * 16 + (lid & 15)) * RS_X
                    + ks * 32 + ((lid >> 4) << 4);
        ldsm4(ah, ab);
        ldsm4(al, ab + (X_LO - X_HI));

        const unsigned char* bp =
            g_w2p + ((size_t)(ks * 2 + wn) << 12) + (lid << 3);
        #pragma unroll
        for (int np = 0; np < 4; np++) {
            uint2 bh0 = __ldg((const uint2*)(bp + (2 * np) * 512));
            uint2 bh1 = __ldg((const uint2*)(bp + (2 * np + 1) * 512));
            uint2 bl0 = __ldg((const uint2*)(bp + (2 * np) * 512 + 256));
            uint2 bl1 = __ldg((const uint2*)(bp + (2 * np + 1) * 512 + 256));
            hmma(acc2[2 * np],     ah, bh0);
            hmma(acc2[2 * np + 1], ah, bh1);
            hmma(acc2[2 * np],     al, bh0);
            hmma(acc2[2 * np + 1], al, bh1);
            hmma(acc2[2 * np],     ah, bl0);
            hmma(acc2[2 * np + 1], ah, bl1);
        }
    }
    __syncthreads();   // X reads done before sred overwrites region

    // ---- epilogue 2: relu(+b2), @W3, reduce, +b3 ----
    float* sred = (float*)smem;    // [2 wn][64 rows][2 outs]
    {
        int r0 = wm * 16 + (lid >> 2);
        float s00 = 0.f, s01 = 0.f, s10 = 0.f, s11 = 0.f;
        #pragma unroll
        for (int nt = 0; nt < 8; nt++) {
            int c = wn * 64 + nt * 8 + (lid & 3) * 2;
            float bb0 = __ldg(b2v + c), bb1 = __ldg(b2v + c + 1);
            float x0 = fmaxf(acc2[nt][0] + bb0, 0.f);
            float x1 = fmaxf(acc2[nt][1] + bb1, 0.f);
            float x2 = fmaxf(acc2[nt][2] + bb0, 0.f);
            float x3 = fmaxf(acc2[nt][3] + bb1, 0.f);
            float w00 = __ldg(W3 + c * 2),       w01 = __ldg(W3 + c * 2 + 1);
            float w10 = __ldg(W3 + (c + 1) * 2), w11 = __ldg(W3 + (c + 1) * 2 + 1);
            s00 += x0 * w00 + x1 * w10;
            s01 += x0 * w01 + x1 * w11;
            s10 += x2 * w00 + x3 * w10;
            s11 += x2 * w01 + x3 * w11;
        }
        s00 += __shfl_xor_sync(0xffffffffu, s00, 1);
        s00 += __shfl_xor_sync(0xffffffffu, s00, 2);
        s01 += __shfl_xor_sync(0xffffffffu, s01, 1);
        s01 += __shfl_xor_sync(0xffffffffu, s01, 2);
        s10 += __shfl_xor_sync(0xffffffffu, s10, 1);
        s10 += __shfl_xor_sync(0xffffffffu, s10, 2);
        s11 += __shfl_xor_sync(0xffffffffu, s11, 1);
        s11 += __shfl_xor_sync(0xffffffffu, s11, 2);
        if ((lid & 3) == 0) {
            sred[(wn * 64 + r0) * 2 + 0] = s00;
            sred[(wn * 64 + r0) * 2 + 1] = s01;
            sred[(wn * 64 + r0 + 8) * 2 + 0] = s10;
            sred[(wn * 64 + r0 + 8) * 2 + 1] = s11;
        }
    }
    __syncthreads();

    if (tid < 64) {
        int e = e0 + tid;
        if (e < E) {
            out[2 * e + 0] = sred[tid * 2 + 0] + sred[(64 + tid) * 2 + 0] + __ldg(b3 + 0);
            out[2 * e + 1] = sred[tid * 2 + 1] + sred[(64 + tid) * 2 + 1] + __ldg(b3 + 1);
        }
    }
}

extern "C" void kernel_launch(void* const* d_in, const int* in_sizes, int n_in,
                              void* d_out, int out_size)
{
    const float* node = (const float*)d_in[0];
    const int*   src  = (const int*)  d_in[1];
    const int*   dst  = (const int*)  d_in[2];
    const float* W1   = (const float*)d_in[3];
    const float* b1   = (const float*)d_in[4];
    const float* W2   = (const float*)d_in[5];
    const float* b2   = (const float*)d_in[6];
    const float* W3   = (const float*)d_in[7];
    const float* b3   = (const float*)d_in[8];
    float* out = (float*)d_out;

    const int E  = in_sizes[1];
    int nn = in_sizes[0] / 128;
    if (nn > MAXN) nn = MAXN;

    prep_weights<<<320, 256>>>(W1, W2);

    cudaFuncSetAttribute(precompute_P_kernel,
                         cudaFuncAttributeMaxDynamicSharedMemorySize, SMEM_PRE);
    precompute_P_kernel<<<(nn + 127) / 128, 512, SMEM_PRE>>>(node, nn);

    cudaFuncSetAttribute(linker_hmma_kernel,
                         cudaFuncAttributeMaxDynamicSharedMemorySize, SMEM_BYTES);
    const int grid = (E + MTILE - 1) / MTILE;
    linker_hmma_kernel<<<grid, THREADS, SMEM_BYTES>>>(
        node, src, dst, b1, b2, W3, b3, out, E);
}

// round 13
// speedup vs baseline: 1.6512x; 1.0414x over previous
#include <cuda_runtime.h>
#include <cuda_bf16.h>
#include <cuda_fp16.h>
#include <math.h>
#include <stdint.h>

// EntityLinker via bf16 split-precision mma.sync (HMMA fallback, base sm_103).
//
// Round-13 (from round-12 base, 883us / rel_err 1.56e-4):
//  - P-gather (P0[src]+P1[dst]) moved from epilogue-1 into the gather phase:
//    prefetched via LDG.128 and summed (__hadd2) into a 32KB smem buffer PS.
//    Its L2 latency now pools with the node-row gathers instead of being
//    exposed between layer-1 and layer-2. Epilogue-1 reads PS via LDS.
//  - smem 70 -> 100.5KB per CTA; still 2 CTAs/SM (201KB < 228KB).
//  - Keeps: fp16 P tables (51MB, L2-resident), layer-1 nonlinear-segs-only
//    (|diff|, prod), MTILE=64 / 256 thr / 2 CTAs/SM.
//
// Precision: x = x_hi(bf16) + x_lo(bf16 residual); 3 MMA terms
// (Ah@Bh + Al@Bh + Ah@Bl), fp32 accumulate inside mma.sync. P tables fp16.

#define THREADS 256
#define MTILE 64
#define MAXN 50176

// smem layout, main kernel (bytes)
#define RS_A   272u            // 128 bf16 + 8 pad (LDSM conflict-free)
#define A_TILE 17408u          // 64 rows * 272
#define S0H    0u              // |diff| A hi [64 x 128] bf16
#define S0L    17408u          // |diff| A lo
#define S1H    34816u          // prod A hi
#define S1L    52224u          // prod A lo
#define RS_X   528u            // 256 bf16 + 8 pad
#define X_HI   0u              // layer2 A hi [64 x 256] (aliases S tiles)
#define X_LO   33792u          // layer2 A lo
#define PS_OFF 69632u          // P-sum buffer [64 rows][128 half2] = 32KB
#define IDX_OFF 102400u
#define SMEM_BYTES 102912
#define SMEM_PRE   69632       // precompute kernel: 128-row A hi/lo tiles

// packed weights: W1 4seg x 8ks x 2wn x 16nt x 2part x 32lane x 8B = 512KB
//                 W2 16ks x 2wn x 8nt x 2part x 32lane x 8B = 128KB
__device__ __align__(256) unsigned char g_w1p[524288];
__device__ __align__(256) unsigned char g_w2p[131072];
// per-node linear-segment outputs, fp16 [node][256]
__device__ __align__(256) __half g_P0[(size_t)MAXN * 256];
__device__ __align__(256) __half g_P1[(size_t)MAXN * 256];

// ---------------- helpers ----------------

__device__ __forceinline__ uint32_t smem_u32(const void* p) {
    uint32_t a;
    asm("{ .reg .u64 t; cvta.to.shared.u64 t, %1; cvt.u32.u64 %0, t; }"
        : "=r"(a) : "l"(p));
    return a;
}

__device__ __forceinline__ void split2(float a, float b, uint32_t& h, uint32_t& l) {
    __nv_bfloat162 hh = __floats2bfloat162_rn(a, b);
    h = *reinterpret_cast<uint32_t*>(&hh);
    __nv_bfloat162 ll = __floats2bfloat162_rn(a - __bfloat162float(hh.x),
                                              b - __bfloat162float(hh.y));
    l = *reinterpret_cast<uint32_t*>(&ll);
}

__device__ __forceinline__ void ldsm4(uint32_t* r, uint32_t addr) {
    asm volatile("ldmatrix.sync.aligned.m8n8.x4.shared.b16 {%0,%1,%2,%3}, [%4];"
                 : "=r"(r[0]), "=r"(r[1]), "=r"(r[2]), "=r"(r[3]) : "r"(addr));
}

__device__ __forceinline__ void hmma(float* d, const uint32_t* a, uint2 b) {
    asm volatile(
        "mma.sync.aligned.m16n8k16.row.col.f32.bf16.bf16.f32 "
        "{%0,%1,%2,%3}, {%4,%5,%6,%7}, {%8,%9}, {%0,%1,%2,%3};"
        : "+f"(d[0]), "+f"(d[1]), "+f"(d[2]), "+f"(d[3])
        : "r"(a[0]), "r"(a[1]), "r"(a[2]), "r"(a[3]), "r"(b.x), "r"(b.y));
}

__device__ __forceinline__ uint32_t hadd2u(uint32_t a, uint32_t b) {
    __half2 r = __hadd2(*reinterpret_cast<__half2*>(&a),
                        *reinterpret_cast<__half2*>(&b));
    return *reinterpret_cast<uint32_t*>(&r);
}

// ---------------- prep: pack W1/W2 fragment-major, bf16 hi/lo ----------------

__global__ void prep_weights(const float* __restrict__ W1,
                             const float* __restrict__ W2) {
    int t = blockIdx.x * blockDim.x + threadIdx.x;
    if (t < 65536) {
        int reg  = t & 1;
        int lane = (t >> 1) & 31;
        int site = t >> 6;
        int nt   = site & 15;
        int rest = site >> 4;           // (seg*8+ks)*2+wn
        int wn   = rest & 1;
        int ks   = (rest >> 1) & 7;
        int seg  = rest >> 4;
        int n  = wn * 128 + nt * 8 + (lane >> 2);
        int k0 = seg * 128 + ks * 16 + (lane & 3) * 2 + reg * 8;
        float w0 = W1[k0 * 256 + n];
        float w1 = W1[(k0 + 1) * 256 + n];
        uint32_t h, l;
        split2(w0, w1, h, l);
        size_t base = (size_t)site * 512 + lane * 8 + reg * 4;
        *(uint32_t*)(g_w1p + base)       = h;
        *(uint32_t*)(g_w1p + base + 256) = l;
    } else if (t < 65536 + 16384) {
        int u = t - 65536;
        int reg  = u & 1;
        int lane = (u >> 1) & 31;
        int site = u >> 6;              // (ks*2+wn)*8+nt
        int nt   = site & 7;
        int rest = site >> 3;
        int wn   = rest & 1;
        int ks   = rest >> 1;
        int n  = wn * 64 + nt * 8 + (lane >> 2);
        int k0 = ks * 16 + (lane & 3) * 2 + reg * 8;
        float w0 = W2[k0 * 128 + n];
        float w1 = W2[(k0 + 1) * 128 + n];
        uint32_t h, l;
        split2(w0, w1, h, l);
        size_t base = (size_t)site * 512 + lane * 8 + reg * 4;
        *(uint32_t*)(g_w2p + base)       = h;
        *(uint32_t*)(g_w2p + base + 256) = l;
    }
}

// ---------------- precompute: P0/P1 = node @ W1_seg{0,1}, fp16 out ----------------

__global__ void __launch_bounds__(512, 1)
precompute_P_kernel(const float* __restrict__ node, int nn)
{
    extern __shared__ unsigned char smem[];
    const uint32_t sb = smem_u32(smem);
    const int tid = threadIdx.x;
    const int lid = tid & 31;
    const int wid = tid >> 5;
    const int wm  = wid & 7;
    const int wn  = wid >> 3;
    const int n0  = blockIdx.x * 128;

    // build A tiles (node rows, bf16 hi/lo), 128 rows
    #pragma unroll
    for (int it = 0; it < 8; it++) {
        int m = it * 16 + wid;
        int row = n0 + m;
        if (row >= nn) row = nn - 1;
        float4 v = __ldg((const float4*)node + (size_t)row * 32 + lid);
        uint32_t h01, l01, h23, l23;
        split2(v.x, v.y, h01, l01);
        split2(v.z, v.w, h23, l23);
        uint32_t off = m * RS_A + lid * 8;
        *(uint2*)(smem + off)          = make_uint2(h01, h23);
        *(uint2*)(smem + off + 34816u) = make_uint2(l01, l23);
    }
    __syncthreads();

    #pragma unroll 1
    for (int p = 0; p < 2; p++) {
        float acc[16][4];
        #pragma unroll
        for (int nt = 0; nt < 16; nt++)
            #pragma unroll
            for (int j = 0; j < 4; j++) acc[nt][j] = 0.f;

        #pragma unroll 1
        for (int ks = 0; ks < 8; ks++) {
            uint32_t ah[4], al[4];
            uint32_t ab = sb + (wm * 16 + (lid & 15)) * RS_A
                        + ks * 32 + ((lid >> 4) << 4);
            ldsm4(ah, ab);
            ldsm4(al, ab + 34816u);
            const unsigned char* bp =
                g_w1p + ((size_t)(((p << 3) + ks) * 2 + wn) << 13) + (lid << 3);
            #pragma unroll
            for (int np = 0; np < 8; np++) {
                uint2 bh0 = __ldg((const uint2*)(bp + (2 * np) * 512));
                uint2 bh1 = __ldg((const uint2*)(bp + (2 * np + 1) * 512));
                uint2 bl0 = __ldg((const uint2*)(bp + (2 * np) * 512 + 256));
                uint2 bl1 = __ldg((const uint2*)(bp + (2 * np + 1) * 512 + 256));
                hmma(acc[2 * np],     ah, bh0);
                hmma(acc[2 * np + 1], ah, bh1);
                hmma(acc[2 * np],     al, bh0);
                hmma(acc[2 * np + 1], al, bh1);
                hmma(acc[2 * np],     ah, bl0);
                hmma(acc[2 * np + 1], ah, bl1);
            }
        }

        __half2* P = (__half2*)(p ? g_P1 : g_P0);
        int r0 = n0 + wm * 16 + (lid >> 2);
        #pragma unroll
        for (int nt = 0; nt < 16; nt++) {
            int c = wn * 128 + nt * 8 + (lid & 3) * 2;
            if (r0 < nn)
                P[(size_t)r0 * 128 + (c >> 1)] = __floats2half2_rn(acc[nt][0], acc[nt][1]);
            if (r0 + 8 < nn)
                P[(size_t)(r0 + 8) * 128 + (c >> 1)] = __floats2half2_rn(acc[nt][2], acc[nt][3]);
        }
    }
}

// ---------------- main kernel ----------------

__global__ void __launch_bounds__(THREADS, 2)
linker_hmma_kernel(const float* __restrict__ node,
                   const int* __restrict__ src, const int* __restrict__ dst,
                   const float* __restrict__ b1v, const float* __restrict__ b2v,
                   const float* __restrict__ W3, const float* __restrict__ b3,
                   float* __restrict__ out, int E)
{
    extern __shared__ unsigned char smem[];
    const uint32_t sb = smem_u32(smem);
    const int tid = threadIdx.x;
    const int lid = tid & 31;
    const int wid = tid >> 5;
    const int wm  = wid & 3;        // M-warp: rows 16*wm .. +15
    const int wn  = wid >> 2;       // N-warp (0/1)
    const int e0  = blockIdx.x * MTILE;

    // ---- edge indices ----
    int* s_idx = (int*)(smem + IDX_OFF);
    if (tid < 128) {
        int e = e0 + (tid & 63);
        int v = 0;
        if (e < E) v = (tid < 64) ? __ldg(src + e) : __ldg(dst + e);
        s_idx[tid] = v;
    }
    __syncthreads();

    // ---- gather h_i/h_j (fp32) -> build |diff| and prod tiles directly ----
    #pragma unroll
    for (int it = 0; it < 8; it++) {
        int lin = it * THREADS + tid;
        int m = lin >> 5, q = lin & 31;
        int rs = s_idx[m], rd = s_idx[64 + m];
        float4 vi = __ldg((const float4*)node + (size_t)rs * 32 + q);
        float4 vj = __ldg((const float4*)node + (size_t)rd * 32 + q);
        uint32_t off = m * RS_A + q * 8;
        uint32_t h01, l01, h23, l23;
        split2(fabsf(vi.x - vj.x), fabsf(vi.y - vj.y), h01, l01);
        split2(fabsf(vi.z - vj.z), fabsf(vi.w - vj.w), h23, l23);
        *(uint2*)(smem + S0H + off) = make_uint2(h01, h23);
        *(uint2*)(smem + S0L + off) = make_uint2(l01, l23);
        split2(vi.x * vj.x, vi.y * vj.y, h01, l01);
        split2(vi.z * vj.z, vi.w * vj.w, h23, l23);
        *(uint2*)(smem + S1H + off) = make_uint2(h01, h23);
        *(uint2*)(smem + S1L + off) = make_uint2(l01, l23);
    }

    // ---- prefetch P0[src]+P1[dst] -> PS smem (pools latency with gather) ----
    #pragma unroll
    for (int it = 0; it < 8; it++) {
        int lin = it * THREADS + tid;
        int m  = lin >> 5;          // edge row 0..63
        int ch = lin & 31;          // 16B chunk within the 512B row
        const uint4* p0 = (const uint4*)((const unsigned char*)g_P0
                          + (size_t)s_idx[m] * 512) + ch;
        const uint4* p1 = (const uint4*)((const unsigned char*)g_P1
                          + (size_t)s_idx[64 + m] * 512) + ch;
        uint4 a = __ldg(p0);
        uint4 b = __ldg(p1);
        uint4 s;
        s.x = hadd2u(a.x, b.x);
        s.y = hadd2u(a.y, b.y);
        s.z = hadd2u(a.z, b.z);
        s.w = hadd2u(a.w, b.w);
        *(uint4*)(smem + PS_OFF + m * 512 + ch * 16) = s;
    }
    __syncthreads();

    // ================= layer 1 (nonlinear segs only: W1 segs 2,3) =================
    float acc[16][4];
    #pragma unroll
    for (int nt = 0; nt < 16; nt++)
        #pragma unroll
        for (int j = 0; j < 4; j++) acc[nt][j] = 0.f;

    #pragma unroll 1
    for (int sg = 0; sg < 2; sg++) {
        const uint32_t abase = sg ? S1H : S0H;
        #pragma unroll 1
        for (int ks = 0; ks < 8; ks++) {
            uint32_t ah[4], al[4];
            uint32_t ab = sb + abase + (wm * 16 + (lid & 15)) * RS_A
                        + ks * 32 + ((lid >> 4) << 4);
            ldsm4(ah, ab);
            ldsm4(al, ab + A_TILE);

            const unsigned char* bp =
                g_w1p + ((size_t)((((sg + 2) << 3) + ks) * 2 + wn) << 13) + (lid << 3);
            #pragma unroll
            for (int np = 0; np < 8; np++) {
                uint2 bh0 = __ldg((const uint2*)(bp + (2 * np) * 512));
                uint2 bh1 = __ldg((const uint2*)(bp + (2 * np + 1) * 512));
                uint2 bl0 = __ldg((const uint2*)(bp + (2 * np) * 512 + 256));
                uint2 bl1 = __ldg((const uint2*)(bp + (2 * np + 1) * 512 + 256));
                hmma(acc[2 * np],     ah, bh0);
                hmma(acc[2 * np + 1], ah, bh1);
                hmma(acc[2 * np],     al, bh0);
                hmma(acc[2 * np + 1], al, bh1);
                hmma(acc[2 * np],     ah, bl0);
                hmma(acc[2 * np + 1], ah, bl1);
            }
        }
    }
    __syncthreads();   // all ldsm of S tiles done before X overwrites them

    // ---- epilogue 1: + PS + b1, relu, split, store x1 ----
    {
        int r0 = wm * 16 + (lid >> 2);
        #pragma unroll
        for (int nt = 0; nt < 16; nt++) {
            int c = wn * 128 + nt * 8 + (lid & 3) * 2;
            int c2 = c >> 1;
            float2 bb = __ldg((const float2*)(b1v + c));
            uint32_t pa = *(uint32_t*)(smem + PS_OFF + r0 * 512 + c2 * 4);
            uint32_t pb = *(uint32_t*)(smem + PS_OFF + (r0 + 8) * 512 + c2 * 4);
            float2 qa = __half22float2(*reinterpret_cast<__half2*>(&pa));
            float2 qb = __half22float2(*reinterpret_cast<__half2*>(&pb));
            float v0 = fmaxf(acc[nt][0] + bb.x + qa.x, 0.f);
            float v1 = fmaxf(acc[nt][1] + bb.y + qa.y, 0.f);
            float v2 = fmaxf(acc[nt][2] + bb.x + qb.x, 0.f);
            float v3 = fmaxf(acc[nt][3] + bb.y + qb.y, 0.f);
            uint32_t h, l;
            split2(v0, v1, h, l);
            *(uint32_t*)(smem + X_HI + r0 * RS_X + c * 2) = h;
            *(uint32_t*)(smem + X_LO + r0 * RS_X + c * 2) = l;
            split2(v2, v3, h, l);
            *(uint32_t*)(smem + X_HI + (r0 + 8) * RS_X + c * 2) = h;
            *(uint32_t*)(smem + X_LO + (r0 + 8) * RS_X + c * 2) = l;
        }
    }
    __syncthreads();

    // ================= layer 2 =================
    float acc2[8][4];
    #pragma unroll
    for (int nt = 0; nt < 8; nt++)
        #pragma unroll
        for (int j = 0; j < 4; j++) acc2[nt][j] = 0.f;

    #pragma unroll 1
    for (int ks = 0; ks < 16; ks++) {
        uint32_t ah[4], al[4];
        uint32_t ab = sb + X_HI + (wm * 16 + (lid & 15)) * RS_X
                    + ks * 32 + ((lid >> 4) << 4);
        ldsm4(ah, ab);
        ldsm4(al, ab + (X_LO - X_HI));

        const unsigned char* bp =
            g_w2p + ((size_t)(ks * 2 + wn) << 12) + (lid << 3);
        #pragma unroll
        for (int np = 0; np < 4; np++) {
            uint2 bh0 = __ldg((const uint2*)(bp + (2 * np) * 512));
            uint2 bh1 = __ldg((const uint2*)(bp + (2 * np + 1) * 512));
            uint2 bl0 = __ldg((const uint2*)(bp + (2 * np) * 512 + 256));
            uint2 bl1 = __ldg((const uint2*)(bp + (2 * np + 1) * 512 + 256));
            hmma(acc2[2 * np],     ah, bh0);
            hmma(acc2[2 * np + 1], ah, bh1);
            hmma(acc2[2 * np],     al, bh0);
            hmma(acc2[2 * np + 1], al, bh1);
            hmma(acc2[2 * np],     ah, bl0);
            hmma(acc2[2 * np + 1], ah, bl1);
        }
    }
    __syncthreads();   // X reads done before sred overwrites region

    // ---- epilogue 2: relu(+b2), @W3, reduce, +b3 ----
    float* sred = (float*)smem;    // [2 wn][64 rows][2 outs]
    {
        int r0 = wm * 16 + (lid >> 2);
        float s00 = 0.f, s01 = 0.f, s10 = 0.f, s11 = 0.f;
        #pragma unroll
        for (int nt = 0; nt < 8; nt++) {
            int c = wn * 64 + nt * 8 + (lid & 3) * 2;
            float bb0 = __ldg(b2v + c), bb1 = __ldg(b2v + c + 1);
            float x0 = fmaxf(acc2[nt][0] + bb0, 0.f);
            float x1 = fmaxf(acc2[nt][1] + bb1, 0.f);
            float x2 = fmaxf(acc2[nt][2] + bb0, 0.f);
            float x3 = fmaxf(acc2[nt][3] + bb1, 0.f);
            float w00 = __ldg(W3 + c * 2),       w01 = __ldg(W3 + c * 2 + 1);
            float w10 = __ldg(W3 + (c + 1) * 2), w11 = __ldg(W3 + (c + 1) * 2 + 1);
            s00 += x0 * w00 + x1 * w10;
            s01 += x0 * w01 + x1 * w11;
            s10 += x2 * w00 + x3 * w10;
            s11 += x2 * w01 + x3 * w11;
        }
        s00 += __shfl_xor_sync(0xffffffffu, s00, 1);
        s00 += __shfl_xor_sync(0xffffffffu, s00, 2);
        s01 += __shfl_xor_sync(0xffffffffu, s01, 1);
        s01 += __shfl_xor_sync(0xffffffffu, s01, 2);
        s10 += __shfl_xor_sync(0xffffffffu, s10, 1);
        s10 += __shfl_xor_sync(0xffffffffu, s10, 2);
        s11 += __shfl_xor_sync(0xffffffffu, s11, 1);
        s11 += __shfl_xor_sync(0xffffffffu, s11, 2);
        if ((lid & 3) == 0) {
            sred[(wn * 64 + r0) * 2 + 0] = s00;
            sred[(wn * 64 + r0) * 2 + 1] = s01;
            sred[(wn * 64 + r0 + 8) * 2 + 0] = s10;
            sred[(wn * 64 + r0 + 8) * 2 + 1] = s11;
        }
    }
    __syncthreads();

    if (tid < 64) {
        int e = e0 + tid;
        if (e < E) {
            out[2 * e + 0] = sred[tid * 2 + 0] + sred[(64 + tid) * 2 + 0] + __ldg(b3 + 0);
            out[2 * e + 1] = sred[tid * 2 + 1] + sred[(64 + tid) * 2 + 1] + __ldg(b3 + 1);
        }
    }
}

extern "C" void kernel_launch(void* const* d_in, const int* in_sizes, int n_in,
                              void* d_out, int out_size)
{
    const float* node = (const float*)d_in[0];
    const int*   src  = (const int*)  d_in[1];
    const int*   dst  = (const int*)  d_in[2];
    const float* W1   = (const float*)d_in[3];
    const float* b1   = (const float*)d_in[4];
    const float* W2   = (const float*)d_in[5];
    const float* b2   = (const float*)d_in[6];
    const float* W3   = (const float*)d_in[7];
    const float* b3   = (const float*)d_in[8];
    float* out = (float*)d_out;

    const int E  = in_sizes[1];
    int nn = in_sizes[0] / 128;
    if (nn > MAXN) nn = MAXN;

    prep_weights<<<320, 256>>>(W1, W2);

    cudaFuncSetAttribute(precompute_P_kernel,
                         cudaFuncAttributeMaxDynamicSharedMemorySize, SMEM_PRE);
    precompute_P_kernel<<<(nn + 127) / 128, 512, SMEM_PRE>>>(node, nn);

    cudaFuncSetAttribute(linker_hmma_kernel,
                         cudaFuncAttributeMaxDynamicSharedMemorySize, SMEM_BYTES);
    const int grid = (E + MTILE - 1) / MTILE;
    linker_hmma_kernel<<<grid, THREADS, SMEM_BYTES>>>(
        node, src, dst, b1, b2, W3, b3, out, E);
}

// round 14
// speedup vs baseline: 2.0648x; 1.2505x over previous
#include <cuda_runtime.h>
#include <cuda_bf16.h>
#include <cuda_fp16.h>
#include <math.h>
#include <stdint.h>

// EntityLinker via mixed-precision mma.sync (HMMA fallback, base sm_103).
//
// Round-14 (from round-13 base, 848us / rel_err 2.3e-4):
//  - fp16 2-term split replaces bf16 3-term in the MAIN kernel:
//    A = Ah(fp16) + Al(fp16 residual), B = single fp16.
//    D = Ah@Bh + Al@Bh  -> 2 HMMAs per logical MMA instead of 3 (-33% MMA).
//    Residual error = B fp16 rounding ~2^-12 per layer (~2.4e-4), added to
//    the existing fp16-P-table error (2.3e-4): predicted total ~5e-4 < 1e-3.
//  - Precompute of P0/P1 stays bf16 3-term (negligible cost, keeps P quality).
//  - Keeps: fp16 P tables (L2-resident), layer-1 nonlinear segs only,
//    P-prefetch into smem during gather, MTILE=64 / 256thr / 2 CTAs/SM.

#define THREADS 256
#define MTILE 64
#define MAXN 50176

// smem layout, main kernel (bytes)
#define RS_A   272u            // 128 fp16 + 8 pad (LDSM conflict-free)
#define A_TILE 17408u          // 64 rows * 272
#define S0H    0u              // |diff| A hi [64 x 128] fp16
#define S0L    17408u          // |diff| A lo
#define S1H    34816u          // prod A hi
#define S1L    52224u          // prod A lo
#define RS_X   528u            // 256 fp16 + 8 pad
#define X_HI   0u              // layer2 A hi [64 x 256] (aliases S tiles)
#define X_LO   33792u          // layer2 A lo
#define PS_OFF 69632u          // P-sum buffer [64 rows][128 half2] = 32KB
#define IDX_OFF 102400u
#define SMEM_BYTES 102912
#define SMEM_PRE   69632       // precompute kernel: 128-row A hi/lo tiles

// packed weights:
//  g_w1p: bf16 hi/lo, W1 all 4 segs (precompute uses segs 0,1) = 512KB
//  g_w1h: fp16 single, W1 segs 2,3: 512 sites x 256B = 128KB
//  g_w2h: fp16 single, W2: 256 sites x 256B = 64KB
__device__ __align__(256) unsigned char g_w1p[524288];
__device__ __align__(256) unsigned char g_w1h[131072];
__device__ __align__(256) unsigned char g_w2h[65536];
// per-node linear-segment outputs, fp16 [node][256]
__device__ __align__(256) __half g_P0[(size_t)MAXN * 256];
__device__ __align__(256) __half g_P1[(size_t)MAXN * 256];

// ---------------- helpers ----------------

__device__ __forceinline__ uint32_t smem_u32(const void* p) {
    uint32_t a;
    asm("{ .reg .u64 t; cvta.to.shared.u64 t, %1; cvt.u32.u64 %0, t; }"
        : "=r"(a) : "l"(p));
    return a;
}

// bf16 split (precompute path)
__device__ __forceinline__ void split2(float a, float b, uint32_t& h, uint32_t& l) {
    __nv_bfloat162 hh = __floats2bfloat162_rn(a, b);
    h = *reinterpret_cast<uint32_t*>(&hh);
    __nv_bfloat162 ll = __floats2bfloat162_rn(a - __bfloat162float(hh.x),
                                              b - __bfloat162float(hh.y));
    l = *reinterpret_cast<uint32_t*>(&ll);
}

// fp16 split (main path)
__device__ __forceinline__ void split2h(float a, float b, uint32_t& h, uint32_t& l) {
    __half2 hh = __floats2half2_rn(a, b);
    h = *reinterpret_cast<uint32_t*>(&hh);
    __half2 ll = __floats2half2_rn(a - __half2float(hh.x),
                                   b - __half2float(hh.y));
    l = *reinterpret_cast<uint32_t*>(&ll);
}

__device__ __forceinline__ void ldsm4(uint32_t* r, uint32_t addr) {
    asm volatile("ldmatrix.sync.aligned.m8n8.x4.shared.b16 {%0,%1,%2,%3}, [%4];"
                 : "=r"(r[0]), "=r"(r[1]), "=r"(r[2]), "=r"(r[3]) : "r"(addr));
}

__device__ __forceinline__ void hmma_bf(float* d, const uint32_t* a, uint2 b) {
    asm volatile(
        "mma.sync.aligned.m16n8k16.row.col.f32.bf16.bf16.f32 "
        "{%0,%1,%2,%3}, {%4,%5,%6,%7}, {%8,%9}, {%0,%1,%2,%3};"
        : "+f"(d[0]), "+f"(d[1]), "+f"(d[2]), "+f"(d[3])
        : "r"(a[0]), "r"(a[1]), "r"(a[2]), "r"(a[3]), "r"(b.x), "r"(b.y));
}

__device__ __forceinline__ void hmma_h(float* d, const uint32_t* a, uint2 b) {
    asm volatile(
        "mma.sync.aligned.m16n8k16.row.col.f32.f16.f16.f32 "
        "{%0,%1,%2,%3}, {%4,%5,%6,%7}, {%8,%9}, {%0,%1,%2,%3};"
        : "+f"(d[0]), "+f"(d[1]), "+f"(d[2]), "+f"(d[3])
        : "r"(a[0]), "r"(a[1]), "r"(a[2]), "r"(a[3]), "r"(b.x), "r"(b.y));
}

__device__ __forceinline__ uint32_t hadd2u(uint32_t a, uint32_t b) {
    __half2 r = __hadd2(*reinterpret_cast<__half2*>(&a),
                        *reinterpret_cast<__half2*>(&b));
    return *reinterpret_cast<uint32_t*>(&r);
}

// ---------------- prep: pack weights ----------------

__global__ void prep_weights(const float* __restrict__ W1,
                             const float* __restrict__ W2) {
    int t = blockIdx.x * blockDim.x + threadIdx.x;
    if (t < 65536) {
        // bf16 hi/lo W1 (all segs; precompute uses 0,1)
        int reg  = t & 1;
        int lane = (t >> 1) & 31;
        int site = t >> 6;
        int nt   = site & 15;
        int rest = site >> 4;           // (seg*8+ks)*2+wn
        int wn   = rest & 1;
        int ks   = (rest >> 1) & 7;
        int seg  = rest >> 4;
        int n  = wn * 128 + nt * 8 + (lane >> 2);
        int k0 = seg * 128 + ks * 16 + (lane & 3) * 2 + reg * 8;
        float w0 = W1[k0 * 256 + n];
        float w1 = W1[(k0 + 1) * 256 + n];
        uint32_t h, l;
        split2(w0, w1, h, l);
        size_t base = (size_t)site * 512 + lane * 8 + reg * 4;
        *(uint32_t*)(g_w1p + base)       = h;
        *(uint32_t*)(g_w1p + base + 256) = l;
    } else if (t < 98304) {
        // fp16 single, W1 segs 2,3
        int u = t - 65536;
        int reg  = u & 1;
        int lane = (u >> 1) & 31;
        int site = u >> 6;              // ((sg*8+ks)*2+wn)*16+nt, sg in {0,1}
        int nt   = site & 15;
        int rest = site >> 4;
        int wn   = rest & 1;
        int ks   = (rest >> 1) & 7;
        int sg   = rest >> 4;
        int n  = wn * 128 + nt * 8 + (lane >> 2);
        int k0 = (sg + 2) * 128 + ks * 16 + (lane & 3) * 2 + reg * 8;
        __half2 w = __floats2half2_rn(W1[k0 * 256 + n], W1[(k0 + 1) * 256 + n]);
        *(__half2*)(g_w1h + (size_t)site * 256 + lane * 8 + reg * 4) = w;
    } else if (t < 114688) {
        // fp16 single, W2
        int u = t - 98304;
        int reg  = u & 1;
        int lane = (u >> 1) & 31;
        int site = u >> 6;              // (ks*2+wn)*8+nt
        int nt   = site & 7;
        int rest = site >> 3;
        int wn   = rest & 1;
        int ks   = rest >> 1;
        int n  = wn * 64 + nt * 8 + (lane >> 2);
        int k0 = ks * 16 + (lane & 3) * 2 + reg * 8;
        __half2 w = __floats2half2_rn(W2[k0 * 128 + n], W2[(k0 + 1) * 128 + n]);
        *(__half2*)(g_w2h + (size_t)site * 256 + lane * 8 + reg * 4) = w;
    }
}

// ---------------- precompute: P0/P1 = node @ W1_seg{0,1}, fp16 out ----------------

__global__ void __launch_bounds__(512, 1)
precompute_P_kernel(const float* __restrict__ node, int nn)
{
    extern __shared__ unsigned char smem[];
    const uint32_t sb = smem_u32(smem);
    const int tid = threadIdx.x;
    const int lid = tid & 31;
    const int wid = tid >> 5;
    const int wm  = wid & 7;
    const int wn  = wid >> 3;
    const int n0  = blockIdx.x * 128;

    #pragma unroll
    for (int it = 0; it < 8; it++) {
        int m = it * 16 + wid;
        int row = n0 + m;
        if (row >= nn) row = nn - 1;
        float4 v = __ldg((const float4*)node + (size_t)row * 32 + lid);
        uint32_t h01, l01, h23, l23;
        split2(v.x, v.y, h01, l01);
        split2(v.z, v.w, h23, l23);
        uint32_t off = m * RS_A + lid * 8;
        *(uint2*)(smem + off)          = make_uint2(h01, h23);
        *(uint2*)(smem + off + 34816u) = make_uint2(l01, l23);
    }
    __syncthreads();

    #pragma unroll 1
    for (int p = 0; p < 2; p++) {
        float acc[16][4];
        #pragma unroll
        for (int nt = 0; nt < 16; nt++)
            #pragma unroll
            for (int j = 0; j < 4; j++) acc[nt][j] = 0.f;

        #pragma unroll 1
        for (int ks = 0; ks < 8; ks++) {
            uint32_t ah[4], al[4];
            uint32_t ab = sb + (wm * 16 + (lid & 15)) * RS_A
                        + ks * 32 + ((lid >> 4) << 4);
            ldsm4(ah, ab);
            ldsm4(al, ab + 34816u);
            const unsigned char* bp =
                g_w1p + ((size_t)(((p << 3) + ks) * 2 + wn) << 13) + (lid << 3);
            #pragma unroll
            for (int np = 0; np < 8; np++) {
                uint2 bh0 = __ldg((const uint2*)(bp + (2 * np) * 512));
                uint2 bh1 = __ldg((const uint2*)(bp + (2 * np + 1) * 512));
                uint2 bl0 = __ldg((const uint2*)(bp + (2 * np) * 512 + 256));
                uint2 bl1 = __ldg((const uint2*)(bp + (2 * np + 1) * 512 + 256));
                hmma_bf(acc[2 * np],     ah, bh0);
                hmma_bf(acc[2 * np + 1], ah, bh1);
                hmma_bf(acc[2 * np],     al, bh0);
                hmma_bf(acc[2 * np + 1], al, bh1);
                hmma_bf(acc[2 * np],     ah, bl0);
                hmma_bf(acc[2 * np + 1], ah, bl1);
            }
        }

        __half2* P = (__half2*)(p ? g_P1 : g_P0);
        int r0 = n0 + wm * 16 + (lid >> 2);
        #pragma unroll
        for (int nt = 0; nt < 16; nt++) {
            int c = wn * 128 + nt * 8 + (lid & 3) * 2;
            if (r0 < nn)
                P[(size_t)r0 * 128 + (c >> 1)] = __floats2half2_rn(acc[nt][0], acc[nt][1]);
            if (r0 + 8 < nn)
                P[(size_t)(r0 + 8) * 128 + (c >> 1)] = __floats2half2_rn(acc[nt][2], acc[nt][3]);
        }
    }
}

// ---------------- main kernel ----------------

__global__ void __launch_bounds__(THREADS, 2)
linker_hmma_kernel(const float* __restrict__ node,
                   const int* __restrict__ src, const int* __restrict__ dst,
                   const float* __restrict__ b1v, const float* __restrict__ b2v,
                   const float* __restrict__ W3, const float* __restrict__ b3,
                   float* __restrict__ out, int E)
{
    extern __shared__ unsigned char smem[];
    const uint32_t sb = smem_u32(smem);
    const int tid = threadIdx.x;
    const int lid = tid & 31;
    const int wid = tid >> 5;
    const int wm  = wid & 3;        // M-warp: rows 16*wm .. +15
    const int wn  = wid >> 2;       // N-warp (0/1)
    const int e0  = blockIdx.x * MTILE;

    // ---- edge indices ----
    int* s_idx = (int*)(smem + IDX_OFF);
    if (tid < 128) {
        int e = e0 + (tid & 63);
        int v = 0;
        if (e < E) v = (tid < 64) ? __ldg(src + e) : __ldg(dst + e);
        s_idx[tid] = v;
    }
    __syncthreads();

    // ---- gather h_i/h_j (fp32) -> |diff| and prod tiles (fp16 hi/lo) ----
    #pragma unroll
    for (int it = 0; it < 8; it++) {
        int lin = it * THREADS + tid;
        int m = lin >> 5, q = lin & 31;
        int rs = s_idx[m], rd = s_idx[64 + m];
        float4 vi = __ldg((const float4*)node + (size_t)rs * 32 + q);
        float4 vj = __ldg((const float4*)node + (size_t)rd * 32 + q);
        uint32_t off = m * RS_A + q * 8;
        uint32_t h01, l01, h23, l23;
        split2h(fabsf(vi.x - vj.x), fabsf(vi.y - vj.y), h01, l01);
        split2h(fabsf(vi.z - vj.z), fabsf(vi.w - vj.w), h23, l23);
        *(uint2*)(smem + S0H + off) = make_uint2(h01, h23);
        *(uint2*)(smem + S0L + off) = make_uint2(l01, l23);
        split2h(vi.x * vj.x, vi.y * vj.y, h01, l01);
        split2h(vi.z * vj.z, vi.w * vj.w, h23, l23);
        *(uint2*)(smem + S1H + off) = make_uint2(h01, h23);
        *(uint2*)(smem + S1L + off) = make_uint2(l01, l23);
    }

    // ---- prefetch P0[src]+P1[dst] -> PS smem (pools latency with gather) ----
    #pragma unroll
    for (int it = 0; it < 8; it++) {
        int lin = it * THREADS + tid;
        int m  = lin >> 5;          // edge row 0..63
        int ch = lin & 31;          // 16B chunk within the 512B row
        const uint4* p0 = (const uint4*)((const unsigned char*)g_P0
                          + (size_t)s_idx[m] * 512) + ch;
        const uint4* p1 = (const uint4*)((const unsigned char*)g_P1
                          + (size_t)s_idx[64 + m] * 512) + ch;
        uint4 a = __ldg(p0);
        uint4 b = __ldg(p1);
        uint4 s;
        s.x = hadd2u(a.x, b.x);
        s.y = hadd2u(a.y, b.y);
        s.z = hadd2u(a.z, b.z);
        s.w = hadd2u(a.w, b.w);
        *(uint4*)(smem + PS_OFF + m * 512 + ch * 16) = s;
    }
    __syncthreads();

    // ======== layer 1 (nonlinear segs, fp16 2-term: Ah@B + Al@B) ========
    float acc[16][4];
    #pragma unroll
    for (int nt = 0; nt < 16; nt++)
        #pragma unroll
        for (int j = 0; j < 4; j++) acc[nt][j] = 0.f;

    #pragma unroll 1
    for (int sg = 0; sg < 2; sg++) {
        const uint32_t abase = sg ? S1H : S0H;
        #pragma unroll 1
        for (int ks = 0; ks < 8; ks++) {
            uint32_t ah[4], al[4];
            uint32_t ab = sb + abase + (wm * 16 + (lid & 15)) * RS_A
                        + ks * 32 + ((lid >> 4) << 4);
            ldsm4(ah, ab);
            ldsm4(al, ab + A_TILE);

            const unsigned char* bp =
                g_w1h + ((size_t)(((sg << 3) + ks) * 2 + wn) << 12) + (lid << 3);
            #pragma unroll
            for (int np = 0; np < 8; np++) {
                uint2 b0 = __ldg((const uint2*)(bp + (2 * np) * 256));
                uint2 b1 = __ldg((const uint2*)(bp + (2 * np + 1) * 256));
                hmma_h(acc[2 * np],     ah, b0);
                hmma_h(acc[2 * np + 1], ah, b1);
                hmma_h(acc[2 * np],     al, b0);
                hmma_h(acc[2 * np + 1], al, b1);
            }
        }
    }
    __syncthreads();   // all ldsm of S tiles done before X overwrites them

    // ---- epilogue 1: + PS + b1, relu, fp16 split, store x1 ----
    {
        int r0 = wm * 16 + (lid >> 2);
        #pragma unroll
        for (int nt = 0; nt < 16; nt++) {
            int c = wn * 128 + nt * 8 + (lid & 3) * 2;
            int c2 = c >> 1;
            float2 bb = __ldg((const float2*)(b1v + c));
            uint32_t pa = *(uint32_t*)(smem + PS_OFF + r0 * 512 + c2 * 4);
            uint32_t pb = *(uint32_t*)(smem + PS_OFF + (r0 + 8) * 512 + c2 * 4);
            float2 qa = __half22float2(*reinterpret_cast<__half2*>(&pa));
            float2 qb = __half22float2(*reinterpret_cast<__half2*>(&pb));
            float v0 = fmaxf(acc[nt][0] + bb.x + qa.x, 0.f);
            float v1 = fmaxf(acc[nt][1] + bb.y + qa.y, 0.f);
            float v2 = fmaxf(acc[nt][2] + bb.x + qb.x, 0.f);
            float v3 = fmaxf(acc[nt][3] + bb.y + qb.y, 0.f);
            uint32_t h, l;
            split2h(v0, v1, h, l);
            *(uint32_t*)(smem + X_HI + r0 * RS_X + c * 2) = h;
            *(uint32_t*)(smem + X_LO + r0 * RS_X + c * 2) = l;
            split2h(v2, v3, h, l);
            *(uint32_t*)(smem + X_HI + (r0 + 8) * RS_X + c * 2) = h;
            *(uint32_t*)(smem + X_LO + (r0 + 8) * RS_X + c * 2) = l;
        }
    }
    __syncthreads();

    // ======== layer 2 (fp16 2-term) ========
    float acc2[8][4];
    #pragma unroll
    for (int nt = 0; nt < 8; nt++)
        #pragma unroll
        for (int j = 0; j < 4; j++) acc2[nt][j] = 0.f;

    #pragma unroll 1
    for (int ks = 0; ks < 16; ks++) {
        uint32_t ah[4], al[4];
        uint32_t ab = sb + X_HI + (wm * 16 + (lid & 15)) * RS_X
                    + ks * 32 + ((lid >> 4) << 4);
        ldsm4(ah, ab);
        ldsm4(al, ab + (X_LO - X_HI));

        const unsigned char* bp =
            g_w2h + ((size_t)(ks * 2 + wn) << 11) + (lid << 3);
        #pragma unroll
        for (int np = 0; np < 4; np++) {
            uint2 b0 = __ldg((const uint2*)(bp + (2 * np) * 256));
            uint2 b1 = __ldg((const uint2*)(bp + (2 * np + 1) * 256));
            hmma_h(acc2[2 * np],     ah, b0);
            hmma_h(acc2[2 * np + 1], ah, b1);
            hmma_h(acc2[2 * np],     al, b0);
            hmma_h(acc2[2 * np + 1], al, b1);
        }
    }
    __syncthreads();   // X reads done before sred overwrites region

    // ---- epilogue 2: relu(+b2), @W3, reduce, +b3 ----
    float* sred = (float*)smem;    // [2 wn][64 rows][2 outs]
    {
        int r0 = wm * 16 + (lid >> 2);
        float s00 = 0.f, s01 = 0.f, s10 = 0.f, s11 = 0.f;
        #pragma unroll
        for (int nt = 0; nt < 8; nt++) {
            int c = wn * 64 + nt * 8 + (lid & 3) * 2;
            float bb0 = __ldg(b2v + c), bb1 = __ldg(b2v + c + 1);
            float x0 = fmaxf(acc2[nt][0] + bb0, 0.f);
            float x1 = fmaxf(acc2[nt][1] + bb1, 0.f);
            float x2 = fmaxf(acc2[nt][2] + bb0, 0.f);
            float x3 = fmaxf(acc2[nt][3] + bb1, 0.f);
            float w00 = __ldg(W3 + c * 2),       w01 = __ldg(W3 + c * 2 + 1);
            float w10 = __ldg(W3 + (c + 1) * 2), w11 = __ldg(W3 + (c + 1) * 2 + 1);
            s00 += x0 * w00 + x1 * w10;
            s01 += x0 * w01 + x1 * w11;
            s10 += x2 * w00 + x3 * w10;
            s11 += x2 * w01 + x3 * w11;
        }
        s00 += __shfl_xor_sync(0xffffffffu, s00, 1);
        s00 += __shfl_xor_sync(0xffffffffu, s00, 2);
        s01 += __shfl_xor_sync(0xffffffffu, s01, 1);
        s01 += __shfl_xor_sync(0xffffffffu, s01, 2);
        s10 += __shfl_xor_sync(0xffffffffu, s10, 1);
        s10 += __shfl_xor_sync(0xffffffffu, s10, 2);
        s11 += __shfl_xor_sync(0xffffffffu, s11, 1);
        s11 += __shfl_xor_sync(0xffffffffu, s11, 2);
        if ((lid & 3) == 0) {
            sred[(wn * 64 + r0) * 2 + 0] = s00;
            sred[(wn * 64 + r0) * 2 + 1] = s01;
            sred[(wn * 64 + r0 + 8) * 2 + 0] = s10;
            sred[(wn * 64 + r0 + 8) * 2 + 1] = s11;
        }
    }
    __syncthreads();

    if (tid < 64) {
        int e = e0 + tid;
        if (e < E) {
            out[2 * e + 0] = sred[tid * 2 + 0] + sred[(64 + tid) * 2 + 0] + __ldg(b3 + 0);
            out[2 * e + 1] = sred[tid * 2 + 1] + sred[(64 + tid) * 2 + 1] + __ldg(b3 + 1);
        }
    }
}

extern "C" void kernel_launch(void* const* d_in, const int* in_sizes, int n_in,
                              void* d_out, int out_size)
{
    const float* node = (const float*)d_in[0];
    const int*   src  = (const int*)  d_in[1];
    const int*   dst  = (const int*)  d_in[2];
    const float* W1   = (const float*)d_in[3];
    const float* b1   = (const float*)d_in[4];
    const float* W2   = (const float*)d_in[5];
    const float* b2   = (const float*)d_in[6];
    const float* W3   = (const float*)d_in[7];
    const float* b3   = (const float*)d_in[8];
    float* out = (float*)d_out;

    const int E  = in_sizes[1];
    int nn = in_sizes[0] / 128;
    if (nn > MAXN) nn = MAXN;

    prep_weights<<<448, 256>>>(W1, W2);

    cudaFuncSetAttribute(precompute_P_kernel,
                         cudaFuncAttributeMaxDynamicSharedMemorySize, SMEM_PRE);
    precompute_P_kernel<<<(nn + 127) / 128, 512, SMEM_PRE>>>(node, nn);

    cudaFuncSetAttribute(linker_hmma_kernel,
                         cudaFuncAttributeMaxDynamicSharedMemorySize, SMEM_BYTES);
    const int grid = (E + MTILE - 1) / MTILE;
    linker_hmma_kernel<<<grid, THREADS, SMEM_BYTES>>>(
        node, src, dst, b1, b2, W3, b3, out, E);
}

// round 15
// speedup vs baseline: 2.3480x; 1.1372x over previous
#include <cuda_runtime.h>
#include <cuda_bf16.h>
#include <cuda_fp16.h>
#include <math.h>
#include <stdint.h>

// EntityLinker via mixed-precision mma.sync (HMMA fallback, base sm_103).
//
// Round-15 (from round-14 base, 678us / rel_err 3.88e-4):
//  - Single-fp16 A (residual term dropped) in BOTH main-kernel layers:
//    plain fp16 GEMM, D = A@B per logical MMA. Per-warp HMMA 768 -> 384.
//    Calibrated error model: each fp16 operand stream adds ~2.2e-4 (RMS);
//    predicted total ~5.0e-4 < 1e-3 (measured base 3.88e-4 + 2 new terms).
//  - Gather/split work halves, Al ldsm gone, epilogue stores halve,
//    smem 100.5KB -> 66.5KB.
//  - Keeps: fp16 P tables (L2-resident) via bf16-3-term precompute,
//    layer-1 nonlinear segs only, P-prefetch in gather phase,
//    MTILE=64 / 256thr / 2 CTAs/SM.

#define THREADS 256
#define MTILE 64
#define MAXN 50176

// smem layout, main kernel (bytes)
#define RS_A   272u            // 128 fp16 + 8 pad (LDSM conflict-free)
#define S0H    0u              // |diff| A [64 x 128] fp16 (17408B)
#define S1H    17408u          // prod  A [64 x 128] fp16
#define RS_X   528u            // 256 fp16 + 8 pad
#define X_OFF  0u              // layer2 A [64 x 256] fp16 (33792B, aliases S)
#define PS_OFF 34816u          // P-sum buffer [64 rows][128 half2] = 32KB
#define IDX_OFF 67584u
#define SMEM_BYTES 68096
#define SMEM_PRE   69632       // precompute kernel: 128-row bf16 hi/lo tiles

// packed weights:
//  g_w1p: bf16 hi/lo, W1 all 4 segs (precompute uses segs 0,1) = 512KB
//  g_w1h: fp16 single, W1 segs 2,3: 512 sites x 256B = 128KB
//  g_w2h: fp16 single, W2: 256 sites x 256B = 64KB
__device__ __align__(256) unsigned char g_w1p[524288];
__device__ __align__(256) unsigned char g_w1h[131072];
__device__ __align__(256) unsigned char g_w2h[65536];
// per-node linear-segment outputs, fp16 [node][256]
__device__ __align__(256) __half g_P0[(size_t)MAXN * 256];
__device__ __align__(256) __half g_P1[(size_t)MAXN * 256];

// ---------------- helpers ----------------

__device__ __forceinline__ uint32_t smem_u32(const void* p) {
    uint32_t a;
    asm("{ .reg .u64 t; cvta.to.shared.u64 t, %1; cvt.u32.u64 %0, t; }"
        : "=r"(a) : "l"(p));
    return a;
}

// bf16 split (precompute path)
__device__ __forceinline__ void split2(float a, float b, uint32_t& h, uint32_t& l) {
    __nv_bfloat162 hh = __floats2bfloat162_rn(a, b);
    h = *reinterpret_cast<uint32_t*>(&hh);
    __nv_bfloat162 ll = __floats2bfloat162_rn(a - __bfloat162float(hh.x),
                                              b - __bfloat162float(hh.y));
    l = *reinterpret_cast<uint32_t*>(&ll);
}

__device__ __forceinline__ uint32_t pack_h2(float a, float b) {
    __half2 h = __floats2half2_rn(a, b);
    return *reinterpret_cast<uint32_t*>(&h);
}

__device__ __forceinline__ void ldsm4(uint32_t* r, uint32_t addr) {
    asm volatile("ldmatrix.sync.aligned.m8n8.x4.shared.b16 {%0,%1,%2,%3}, [%4];"
                 : "=r"(r[0]), "=r"(r[1]), "=r"(r[2]), "=r"(r[3]) : "r"(addr));
}

__device__ __forceinline__ void hmma_bf(float* d, const uint32_t* a, uint2 b) {
    asm volatile(
        "mma.sync.aligned.m16n8k16.row.col.f32.bf16.bf16.f32 "
        "{%0,%1,%2,%3}, {%4,%5,%6,%7}, {%8,%9}, {%0,%1,%2,%3};"
        : "+f"(d[0]), "+f"(d[1]), "+f"(d[2]), "+f"(d[3])
        : "r"(a[0]), "r"(a[1]), "r"(a[2]), "r"(a[3]), "r"(b.x), "r"(b.y));
}

__device__ __forceinline__ void hmma_h(float* d, const uint32_t* a, uint2 b) {
    asm volatile(
        "mma.sync.aligned.m16n8k16.row.col.f32.f16.f16.f32 "
        "{%0,%1,%2,%3}, {%4,%5,%6,%7}, {%8,%9}, {%0,%1,%2,%3};"
        : "+f"(d[0]), "+f"(d[1]), "+f"(d[2]), "+f"(d[3])
        : "r"(a[0]), "r"(a[1]), "r"(a[2]), "r"(a[3]), "r"(b.x), "r"(b.y));
}

__device__ __forceinline__ uint32_t hadd2u(uint32_t a, uint32_t b) {
    __half2 r = __hadd2(*reinterpret_cast<__half2*>(&a),
                        *reinterpret_cast<__half2*>(&b));
    return *reinterpret_cast<uint32_t*>(&r);
}

// ---------------- prep: pack weights ----------------

__global__ void prep_weights(const float* __restrict__ W1,
                             const float* __restrict__ W2) {
    int t = blockIdx.x * blockDim.x + threadIdx.x;
    if (t < 65536) {
        // bf16 hi/lo W1 (all segs; precompute uses 0,1)
        int reg  = t & 1;
        int lane = (t >> 1) & 31;
        int site = t >> 6;
        int nt   = site & 15;
        int rest = site >> 4;           // (seg*8+ks)*2+wn
        int wn   = rest & 1;
        int ks   = (rest >> 1) & 7;
        int seg  = rest >> 4;
        int n  = wn * 128 + nt * 8 + (lane >> 2);
        int k0 = seg * 128 + ks * 16 + (lane & 3) * 2 + reg * 8;
        float w0 = W1[k0 * 256 + n];
        float w1 = W1[(k0 + 1) * 256 + n];
        uint32_t h, l;
        split2(w0, w1, h, l);
        size_t base = (size_t)site * 512 + lane * 8 + reg * 4;
        *(uint32_t*)(g_w1p + base)       = h;
        *(uint32_t*)(g_w1p + base + 256) = l;
    } else if (t < 98304) {
        // fp16 single, W1 segs 2,3
        int u = t - 65536;
        int reg  = u & 1;
        int lane = (u >> 1) & 31;
        int site = u >> 6;              // ((sg*8+ks)*2+wn)*16+nt, sg in {0,1}
        int nt   = site & 15;
        int rest = site >> 4;
        int wn   = rest & 1;
        int ks   = (rest >> 1) & 7;
        int sg   = rest >> 4;
        int n  = wn * 128 + nt * 8 + (lane >> 2);
        int k0 = (sg + 2) * 128 + ks * 16 + (lane & 3) * 2 + reg * 8;
        *(uint32_t*)(g_w1h + (size_t)site * 256 + lane * 8 + reg * 4) =
            pack_h2(W1[k0 * 256 + n], W1[(k0 + 1) * 256 + n]);
    } else if (t < 114688) {
        // fp16 single, W2
        int u = t - 98304;
        int reg  = u & 1;
        int lane = (u >> 1) & 31;
        int site = u >> 6;              // (ks*2+wn)*8+nt
        int nt   = site & 7;
        int rest = site >> 3;
        int wn   = rest & 1;
        int ks   = rest >> 1;
        int n  = wn * 64 + nt * 8 + (lane >> 2);
        int k0 = ks * 16 + (lane & 3) * 2 + reg * 8;
        *(uint32_t*)(g_w2h + (size_t)site * 256 + lane * 8 + reg * 4) =
            pack_h2(W2[k0 * 128 + n], W2[(k0 + 1) * 128 + n]);
    }
}

// ---------------- precompute: P0/P1 = node @ W1_seg{0,1}, fp16 out ----------------

__global__ void __launch_bounds__(512, 1)
precompute_P_kernel(const float* __restrict__ node, int nn)
{
    extern __shared__ unsigned char smem[];
    const uint32_t sb = smem_u32(smem);
    const int tid = threadIdx.x;
    const int lid = tid & 31;
    const int wid = tid >> 5;
    const int wm  = wid & 7;
    const int wn  = wid >> 3;
    const int n0  = blockIdx.x * 128;

    #pragma unroll
    for (int it = 0; it < 8; it++) {
        int m = it * 16 + wid;
        int row = n0 + m;
        if (row >= nn) row = nn - 1;
        float4 v = __ldg((const float4*)node + (size_t)row * 32 + lid);
        uint32_t h01, l01, h23, l23;
        split2(v.x, v.y, h01, l01);
        split2(v.z, v.w, h23, l23);
        uint32_t off = m * RS_A + lid * 8;
        *(uint2*)(smem + off)          = make_uint2(h01, h23);
        *(uint2*)(smem + off + 34816u) = make_uint2(l01, l23);
    }
    __syncthreads();

    #pragma unroll 1
    for (int p = 0; p < 2; p++) {
        float acc[16][4];
        #pragma unroll
        for (int nt = 0; nt < 16; nt++)
            #pragma unroll
            for (int j = 0; j < 4; j++) acc[nt][j] = 0.f;

        #pragma unroll 1
        for (int ks = 0; ks < 8; ks++) {
            uint32_t ah[4], al[4];
            uint32_t ab = sb + (wm * 16 + (lid & 15)) * RS_A
                        + ks * 32 + ((lid >> 4) << 4);
            ldsm4(ah, ab);
            ldsm4(al, ab + 34816u);
            const unsigned char* bp =
                g_w1p + ((size_t)(((p << 3) + ks) * 2 + wn) << 13) + (lid << 3);
            #pragma unroll
            for (int np = 0; np < 8; np++) {
                uint2 bh0 = __ldg((const uint2*)(bp + (2 * np) * 512));
                uint2 bh1 = __ldg((const uint2*)(bp + (2 * np + 1) * 512));
                uint2 bl0 = __ldg((const uint2*)(bp + (2 * np) * 512 + 256));
                uint2 bl1 = __ldg((const uint2*)(bp + (2 * np + 1) * 512 + 256));
                hmma_bf(acc[2 * np],     ah, bh0);
                hmma_bf(acc[2 * np + 1], ah, bh1);
                hmma_bf(acc[2 * np],     al, bh0);
                hmma_bf(acc[2 * np + 1], al, bh1);
                hmma_bf(acc[2 * np],     ah, bl0);
                hmma_bf(acc[2 * np + 1], ah, bl1);
            }
        }

        __half2* P = (__half2*)(p ? g_P1 : g_P0);
        int r0 = n0 + wm * 16 + (lid >> 2);
        #pragma unroll
        for (int nt = 0; nt < 16; nt++) {
            int c = wn * 128 + nt * 8 + (lid & 3) * 2;
            if (r0 < nn)
                P[(size_t)r0 * 128 + (c >> 1)] = __floats2half2_rn(acc[nt][0], acc[nt][1]);
            if (r0 + 8 < nn)
                P[(size_t)(r0 + 8) * 128 + (c >> 1)] = __floats2half2_rn(acc[nt][2], acc[nt][3]);
        }
    }
}

// ---------------- main kernel ----------------

__global__ void __launch_bounds__(THREADS, 2)
linker_hmma_kernel(const float* __restrict__ node,
                   const int* __restrict__ src, const int* __restrict__ dst,
                   const float* __restrict__ b1v, const float* __restrict__ b2v,
                   const float* __restrict__ W3, const float* __restrict__ b3,
                   float* __restrict__ out, int E)
{
    extern __shared__ unsigned char smem[];
    const uint32_t sb = smem_u32(smem);
    const int tid = threadIdx.x;
    const int lid = tid & 31;
    const int wid = tid >> 5;
    const int wm  = wid & 3;        // M-warp: rows 16*wm .. +15
    const int wn  = wid >> 2;       // N-warp (0/1)
    const int e0  = blockIdx.x * MTILE;

    // ---- edge indices ----
    int* s_idx = (int*)(smem + IDX_OFF);
    if (tid < 128) {
        int e = e0 + (tid & 63);
        int v = 0;
        if (e < E) v = (tid < 64) ? __ldg(src + e) : __ldg(dst + e);
        s_idx[tid] = v;
    }
    __syncthreads();

    // ---- gather h_i/h_j (fp32) -> |diff| and prod tiles (single fp16) ----
    #pragma unroll
    for (int it = 0; it < 8; it++) {
        int lin = it * THREADS + tid;
        int m = lin >> 5, q = lin & 31;
        int rs = s_idx[m], rd = s_idx[64 + m];
        float4 vi = __ldg((const float4*)node + (size_t)rs * 32 + q);
        float4 vj = __ldg((const float4*)node + (size_t)rd * 32 + q);
        uint32_t off = m * RS_A + q * 8;
        *(uint2*)(smem + S0H + off) = make_uint2(
            pack_h2(fabsf(vi.x - vj.x), fabsf(vi.y - vj.y)),
            pack_h2(fabsf(vi.z - vj.z), fabsf(vi.w - vj.w)));
        *(uint2*)(smem + S1H + off) = make_uint2(
            pack_h2(vi.x * vj.x, vi.y * vj.y),
            pack_h2(vi.z * vj.z, vi.w * vj.w));
    }

    // ---- prefetch P0[src]+P1[dst] -> PS smem (pools latency with gather) ----
    #pragma unroll
    for (int it = 0; it < 8; it++) {
        int lin = it * THREADS + tid;
        int m  = lin >> 5;          // edge row 0..63
        int ch = lin & 31;          // 16B chunk within the 512B row
        const uint4* p0 = (const uint4*)((const unsigned char*)g_P0
                          + (size_t)s_idx[m] * 512) + ch;
        const uint4* p1 = (const uint4*)((const unsigned char*)g_P1
                          + (size_t)s_idx[64 + m] * 512) + ch;
        uint4 a = __ldg(p0);
        uint4 b = __ldg(p1);
        uint4 s;
        s.x = hadd2u(a.x, b.x);
        s.y = hadd2u(a.y, b.y);
        s.z = hadd2u(a.z, b.z);
        s.w = hadd2u(a.w, b.w);
        *(uint4*)(smem + PS_OFF + m * 512 + ch * 16) = s;
    }
    __syncthreads();

    // ======== layer 1 (nonlinear segs, plain fp16: A@B) ========
    float acc[16][4];
    #pragma unroll
    for (int nt = 0; nt < 16; nt++)
        #pragma unroll
        for (int j = 0; j < 4; j++) acc[nt][j] = 0.f;

    #pragma unroll 1
    for (int sg = 0; sg < 2; sg++) {
        const uint32_t abase = sg ? S1H : S0H;
        #pragma unroll 1
        for (int ks = 0; ks < 8; ks++) {
            uint32_t ah[4];
            uint32_t ab = sb + abase + (wm * 16 + (lid & 15)) * RS_A
                        + ks * 32 + ((lid >> 4) << 4);
            ldsm4(ah, ab);

            const unsigned char* bp =
                g_w1h + ((size_t)(((sg << 3) + ks) * 2 + wn) << 12) + (lid << 3);
            #pragma unroll
            for (int np = 0; np < 8; np++) {
                uint2 b0 = __ldg((const uint2*)(bp + (2 * np) * 256));
                uint2 b1 = __ldg((const uint2*)(bp + (2 * np + 1) * 256));
                hmma_h(acc[2 * np],     ah, b0);
                hmma_h(acc[2 * np + 1], ah, b1);
            }
        }
    }
    __syncthreads();   // all ldsm of S tiles done before X overwrites them

    // ---- epilogue 1: + PS + b1, relu, fp16, store x1 ----
    {
        int r0 = wm * 16 + (lid >> 2);
        #pragma unroll
        for (int nt = 0; nt < 16; nt++) {
            int c = wn * 128 + nt * 8 + (lid & 3) * 2;
            int c2 = c >> 1;
            float2 bb = __ldg((const float2*)(b1v + c));
            uint32_t pa = *(uint32_t*)(smem + PS_OFF + r0 * 512 + c2 * 4);
            uint32_t pb = *(uint32_t*)(smem + PS_OFF + (r0 + 8) * 512 + c2 * 4);
            float2 qa = __half22float2(*reinterpret_cast<__half2*>(&pa));
            float2 qb = __half22float2(*reinterpret_cast<__half2*>(&pb));
            *(uint32_t*)(smem + X_OFF + r0 * RS_X + c * 2) =
                pack_h2(fmaxf(acc[nt][0] + bb.x + qa.x, 0.f),
                        fmaxf(acc[nt][1] + bb.y + qa.y, 0.f));
            *(uint32_t*)(smem + X_OFF + (r0 + 8) * RS_X + c * 2) =
                pack_h2(fmaxf(acc[nt][2] + bb.x + qb.x, 0.f),
                        fmaxf(acc[nt][3] + bb.y + qb.y, 0.f));
        }
    }
    __syncthreads();

    // ======== layer 2 (plain fp16) ========
    float acc2[8][4];
    #pragma unroll
    for (int nt = 0; nt < 8; nt++)
        #pragma unroll
        for (int j = 0; j < 4; j++) acc2[nt][j] = 0.f;

    #pragma unroll 1
    for (int ks = 0; ks < 16; ks++) {
        uint32_t ah[4];
        uint32_t ab = sb + X_OFF + (wm * 16 + (lid & 15)) * RS_X
                    + ks * 32 + ((lid >> 4) << 4);
        ldsm4(ah, ab);

        const unsigned char* bp =
            g_w2h + ((size_t)(ks * 2 + wn) << 11) + (lid << 3);
        #pragma unroll
        for (int np = 0; np < 4; np++) {
            uint2 b0 = __ldg((const uint2*)(bp + (2 * np) * 256));
            uint2 b1 = __ldg((const uint2*)(bp + (2 * np + 1) * 256));
            hmma_h(acc2[2 * np],     ah, b0);
            hmma_h(acc2[2 * np + 1], ah, b1);
        }
    }
    __syncthreads();   // X reads done before sred overwrites region

    // ---- epilogue 2: relu(+b2), @W3, reduce, +b3 ----
    float* sred = (float*)smem;    // [2 wn][64 rows][2 outs]
    {
        int r0 = wm * 16 + (lid >> 2);
        float s00 = 0.f, s01 = 0.f, s10 = 0.f, s11 = 0.f;
        #pragma unroll
        for (int nt = 0; nt < 8; nt++) {
            int c = wn * 64 + nt * 8 + (lid & 3) * 2;
            float bb0 = __ldg(b2v + c), bb1 = __ldg(b2v + c + 1);
            float x0 = fmaxf(acc2[nt][0] + bb0, 0.f);
            float x1 = fmaxf(acc2[nt][1] + bb1, 0.f);
            float x2 = fmaxf(acc2[nt][2] + bb0, 0.f);
            float x3 = fmaxf(acc2[nt][3] + bb1, 0.f);
            float w00 = __ldg(W3 + c * 2),       w01 = __ldg(W3 + c * 2 + 1);
            float w10 = __ldg(W3 + (c + 1) * 2), w11 = __ldg(W3 + (c + 1) * 2 + 1);
            s00 += x0 * w00 + x1 * w10;
            s01 += x0 * w01 + x1 * w11;
            s10 += x2 * w00 + x3 * w10;
            s11 += x2 * w01 + x3 * w11;
        }
        s00 += __shfl_xor_sync(0xffffffffu, s00, 1);
        s00 += __shfl_xor_sync(0xffffffffu, s00, 2);
        s01 += __shfl_xor_sync(0xffffffffu, s01, 1);
        s01 += __shfl_xor_sync(0xffffffffu, s01, 2);
        s10 += __shfl_xor_sync(0xffffffffu, s10, 1);
        s10 += __shfl_xor_sync(0xffffffffu, s10, 2);
        s11 += __shfl_xor_sync(0xffffffffu, s11, 1);
        s11 += __shfl_xor_sync(0xffffffffu, s11, 2);
        if ((lid & 3) == 0) {
            sred[(wn * 64 + r0) * 2 + 0] = s00;
            sred[(wn * 64 + r0) * 2 + 1] = s01;
            sred[(wn * 64 + r0 + 8) * 2 + 0] = s10;
            sred[(wn * 64 + r0 + 8) * 2 + 1] = s11;
        }
    }
    __syncthreads();

    if (tid < 64) {
        int e = e0 + tid;
        if (e < E) {
            out[2 * e + 0] = sred[tid * 2 + 0] + sred[(64 + tid) * 2 + 0] + __ldg(b3 + 0);
            out[2 * e + 1] = sred[tid * 2 + 1] + sred[(64 + tid) * 2 + 1] + __ldg(b3 + 1);
        }
    }
}

extern "C" void kernel_launch(void* const* d_in, const int* in_sizes, int n_in,
                              void* d_out, int out_size)
{
    const float* node = (const float*)d_in[0];
    const int*   src  = (const int*)  d_in[1];
    const int*   dst  = (const int*)  d_in[2];
    const float* W1   = (const float*)d_in[3];
    const float* b1   = (const float*)d_in[4];
    const float* W2   = (const float*)d_in[5];
    const float* b2   = (const float*)d_in[6];
    const float* W3   = (const float*)d_in[7];
    const float* b3   = (const float*)d_in[8];
    float* out = (float*)d_out;

    const int E  = in_sizes[1];
    int nn = in_sizes[0] / 128;
    if (nn > MAXN) nn = MAXN;

    prep_weights<<<448, 256>>>(W1, W2);

    cudaFuncSetAttribute(precompute_P_kernel,
                         cudaFuncAttributeMaxDynamicSharedMemorySize, SMEM_PRE);
    precompute_P_kernel<<<(nn + 127) / 128, 512, SMEM_PRE>>>(node, nn);

    cudaFuncSetAttribute(linker_hmma_kernel,
                         cudaFuncAttributeMaxDynamicSharedMemorySize, SMEM_BYTES);
    const int grid = (E + MTILE - 1) / MTILE;
    linker_hmma_kernel<<<grid, THREADS, SMEM_BYTES>>>(
        node, src, dst, b1, b2, W3, b3, out, E);
}

// round 16
// speedup vs baseline: 2.9199x; 1.2435x over previous
#include <cuda_runtime.h>
#include <cuda_bf16.h>
#include <cuda_fp16.h>
#include <math.h>
#include <stdint.h>

// EntityLinker via mixed-precision mma.sync (HMMA fallback, base sm_103).
//
// Round-16 (from round-15 base, 596us / rel_err 4.96e-4):
//  - Warp retile 4Mx2N -> 2Mx4N in both layers: each B fragment feeds 2
//    HMMAs and is loaded by 2 warps/CTA instead of 4 -> L1TEX B-operand
//    traffic ~halves (L1 was co-binding with tensor).
//  - P-prefetch via cp.async.cg into padded (528B stride) P0/P1 staging,
//    issued right after the index load, waited only at the pre-epilogue-1
//    barrier: P L2 latency overlaps gather + all of layer-1; cg bypasses L1.
//    hadd2 fused into epilogue-1. Zero extra barriers (round-9's mistake).
//  - Numerics identical to round 15 (expect same rel_err).
//  - Keeps: plain-fp16 main GEMMs, fp16 P tables via bf16-3-term precompute,
//    layer-1 nonlinear segs only, MTILE=64 / 256thr / 2 CTAs/SM.

#define THREADS 256
#define MTILE 64
#define MAXN 50176

// smem layout, main kernel (bytes)
#define RS_A   272u            // 128 fp16 + 8 pad (LDSM conflict-free)
#define S0H    0u              // |diff| A [64 x 128] fp16 (17408B)
#define S1H    17408u          // prod  A [64 x 128] fp16
#define RS_X   528u            // 256 fp16 + 8 pad
#define X_OFF  0u              // layer2 A [64 x 256] fp16 (33792B, aliases S)
#define RS_P   528u            // padded P staging row stride (bank-spread)
#define P0S    34816u          // P0[src] staging [64 x 528B] = 33792
#define P1S    68608u          // P1[dst] staging
#define IDX_OFF 102400u
#define SMEM_BYTES 102912
#define SMEM_PRE   69632       // precompute kernel: 128-row bf16 hi/lo tiles

// packed weights:
//  g_w1p: bf16 hi/lo, W1 all 4 segs (precompute uses segs 0,1) = 512KB
//  g_w1h: fp16 single, W1 segs 2,3: 512 sites x 256B = 128KB
//  g_w2h: fp16 single, W2: 256 sites x 256B = 64KB
__device__ __align__(256) unsigned char g_w1p[524288];
__device__ __align__(256) unsigned char g_w1h[131072];
__device__ __align__(256) unsigned char g_w2h[65536];
// per-node linear-segment outputs, fp16 [node][256]
__device__ __align__(256) __half g_P0[(size_t)MAXN * 256];
__device__ __align__(256) __half g_P1[(size_t)MAXN * 256];

// ---------------- helpers ----------------

__device__ __forceinline__ uint32_t smem_u32(const void* p) {
    uint32_t a;
    asm("{ .reg .u64 t; cvta.to.shared.u64 t, %1; cvt.u32.u64 %0, t; }"
        : "=r"(a) : "l"(p));
    return a;
}

// bf16 split (precompute path)
__device__ __forceinline__ void split2(float a, float b, uint32_t& h, uint32_t& l) {
    __nv_bfloat162 hh = __floats2bfloat162_rn(a, b);
    h = *reinterpret_cast<uint32_t*>(&hh);
    __nv_bfloat162 ll = __floats2bfloat162_rn(a - __bfloat162float(hh.x),
                                              b - __bfloat162float(hh.y));
    l = *reinterpret_cast<uint32_t*>(&ll);
}

__device__ __forceinline__ uint32_t pack_h2(float a, float b) {
    __half2 h = __floats2half2_rn(a, b);
    return *reinterpret_cast<uint32_t*>(&h);
}

__device__ __forceinline__ void ldsm4(uint32_t* r, uint32_t addr) {
    asm volatile("ldmatrix.sync.aligned.m8n8.x4.shared.b16 {%0,%1,%2,%3}, [%4];"
                 : "=r"(r[0]), "=r"(r[1]), "=r"(r[2]), "=r"(r[3]) : "r"(addr));
}

__device__ __forceinline__ void hmma_bf(float* d, const uint32_t* a, uint2 b) {
    asm volatile(
        "mma.sync.aligned.m16n8k16.row.col.f32.bf16.bf16.f32 "
        "{%0,%1,%2,%3}, {%4,%5,%6,%7}, {%8,%9}, {%0,%1,%2,%3};"
        : "+f"(d[0]), "+f"(d[1]), "+f"(d[2]), "+f"(d[3])
        : "r"(a[0]), "r"(a[1]), "r"(a[2]), "r"(a[3]), "r"(b.x), "r"(b.y));
}

__device__ __forceinline__ void hmma_h(float* d, const uint32_t* a, uint2 b) {
    asm volatile(
        "mma.sync.aligned.m16n8k16.row.col.f32.f16.f16.f32 "
        "{%0,%1,%2,%3}, {%4,%5,%6,%7}, {%8,%9}, {%0,%1,%2,%3};"
        : "+f"(d[0]), "+f"(d[1]), "+f"(d[2]), "+f"(d[3])
        : "r"(a[0]), "r"(a[1]), "r"(a[2]), "r"(a[3]), "r"(b.x), "r"(b.y));
}

__device__ __forceinline__ uint32_t hadd2u(uint32_t a, uint32_t b) {
    __half2 r = __hadd2(*reinterpret_cast<__half2*>(&a),
                        *reinterpret_cast<__half2*>(&b));
    return *reinterpret_cast<uint32_t*>(&r);
}

__device__ __forceinline__ void cp16(uint32_t d, const void* s) {
    asm volatile("cp.async.cg.shared.global [%0], [%1], 16;"
                 :: "r"(d), "l"(s) : "memory");
}
__device__ __forceinline__ void cp_commit() {
    asm volatile("cp.async.commit_group;" ::: "memory");
}
__device__ __forceinline__ void cp_wait_all() {
    asm volatile("cp.async.wait_group 0;" ::: "memory");
}

// ---------------- prep: pack weights ----------------

__global__ void prep_weights(const float* __restrict__ W1,
                             const float* __restrict__ W2) {
    int t = blockIdx.x * blockDim.x + threadIdx.x;
    if (t < 65536) {
        // bf16 hi/lo W1 (all segs; precompute uses 0,1)
        int reg  = t & 1;
        int lane = (t >> 1) & 31;
        int site = t >> 6;
        int nt   = site & 15;
        int rest = site >> 4;           // (seg*8+ks)*2+wn
        int wn   = rest & 1;
        int ks   = (rest >> 1) & 7;
        int seg  = rest >> 4;
        int n  = wn * 128 + nt * 8 + (lane >> 2);
        int k0 = seg * 128 + ks * 16 + (lane & 3) * 2 + reg * 8;
        float w0 = W1[k0 * 256 + n];
        float w1 = W1[(k0 + 1) * 256 + n];
        uint32_t h, l;
        split2(w0, w1, h, l);
        size_t base = (size_t)site * 512 + lane * 8 + reg * 4;
        *(uint32_t*)(g_w1p + base)       = h;
        *(uint32_t*)(g_w1p + base + 256) = l;
    } else if (t < 98304) {
        // fp16 single, W1 segs 2,3
        int u = t - 65536;
        int reg  = u & 1;
        int lane = (u >> 1) & 31;
        int site = u >> 6;              // ((sg*8+ks)*2+wn)*16+nt, sg in {0,1}
        int nt   = site & 15;
        int rest = site >> 4;
        int wn   = rest & 1;
        int ks   = (rest >> 1) & 7;
        int sg   = rest >> 4;
        int n  = wn * 128 + nt * 8 + (lane >> 2);
        int k0 = (sg + 2) * 128 + ks * 16 + (lane & 3) * 2 + reg * 8;
        *(uint32_t*)(g_w1h + (size_t)site * 256 + lane * 8 + reg * 4) =
            pack_h2(W1[k0 * 256 + n], W1[(k0 + 1) * 256 + n]);
    } else if (t < 114688) {
        // fp16 single, W2
        int u = t - 98304;
        int reg  = u & 1;
        int lane = (u >> 1) & 31;
        int site = u >> 6;              // (ks*2+wn)*8+nt
        int nt   = site & 7;
        int rest = site >> 3;
        int wn   = rest & 1;
        int ks   = rest >> 1;
        int n  = wn * 64 + nt * 8 + (lane >> 2);
        int k0 = ks * 16 + (lane & 3) * 2 + reg * 8;
        *(uint32_t*)(g_w2h + (size_t)site * 256 + lane * 8 + reg * 4) =
            pack_h2(W2[k0 * 128 + n], W2[(k0 + 1) * 128 + n]);
    }
}

// ---------------- precompute: P0/P1 = node @ W1_seg{0,1}, fp16 out ----------------

__global__ void __launch_bounds__(512, 1)
precompute_P_kernel(const float* __restrict__ node, int nn)
{
    extern __shared__ unsigned char smem[];
    const uint32_t sb = smem_u32(smem);
    const int tid = threadIdx.x;
    const int lid = tid & 31;
    const int wid = tid >> 5;
    const int wm  = wid & 7;
    const int wn  = wid >> 3;
    const int n0  = blockIdx.x * 128;

    #pragma unroll
    for (int it = 0; it < 8; it++) {
        int m = it * 16 + wid;
        int row = n0 + m;
        if (row >= nn) row = nn - 1;
        float4 v = __ldg((const float4*)node + (size_t)row * 32 + lid);
        uint32_t h01, l01, h23, l23;
        split2(v.x, v.y, h01, l01);
        split2(v.z, v.w, h23, l23);
        uint32_t off = m * RS_A + lid * 8;
        *(uint2*)(smem + off)          = make_uint2(h01, h23);
        *(uint2*)(smem + off + 34816u) = make_uint2(l01, l23);
    }
    __syncthreads();

    #pragma unroll 1
    for (int p = 0; p < 2; p++) {
        float acc[16][4];
        #pragma unroll
        for (int nt = 0; nt < 16; nt++)
            #pragma unroll
            for (int j = 0; j < 4; j++) acc[nt][j] = 0.f;

        #pragma unroll 1
        for (int ks = 0; ks < 8; ks++) {
            uint32_t ah[4], al[4];
            uint32_t ab = sb + (wm * 16 + (lid & 15)) * RS_A
                        + ks * 32 + ((lid >> 4) << 4);
            ldsm4(ah, ab);
            ldsm4(al, ab + 34816u);
            const unsigned char* bp =
                g_w1p + ((size_t)(((p << 3) + ks) * 2 + wn) << 13) + (lid << 3);
            #pragma unroll
            for (int np = 0; np < 8; np++) {
                uint2 bh0 = __ldg((const uint2*)(bp + (2 * np) * 512));
                uint2 bh1 = __ldg((const uint2*)(bp + (2 * np + 1) * 512));
                uint2 bl0 = __ldg((const uint2*)(bp + (2 * np) * 512 + 256));
                uint2 bl1 = __ldg((const uint2*)(bp + (2 * np + 1) * 512 + 256));
                hmma_bf(acc[2 * np],     ah, bh0);
                hmma_bf(acc[2 * np + 1], ah, bh1);
                hmma_bf(acc[2 * np],     al, bh0);
                hmma_bf(acc[2 * np + 1], al, bh1);
                hmma_bf(acc[2 * np],     ah, bl0);
                hmma_bf(acc[2 * np + 1], ah, bl1);
            }
        }

        __half2* P = (__half2*)(p ? g_P1 : g_P0);
        int r0 = n0 + wm * 16 + (lid >> 2);
        #pragma unroll
        for (int nt = 0; nt < 16; nt++) {
            int c = wn * 128 + nt * 8 + (lid & 3) * 2;
            if (r0 < nn)
                P[(size_t)r0 * 128 + (c >> 1)] = __floats2half2_rn(acc[nt][0], acc[nt][1]);
            if (r0 + 8 < nn)
                P[(size_t)(r0 + 8) * 128 + (c >> 1)] = __floats2half2_rn(acc[nt][2], acc[nt][3]);
        }
    }
}

// ---------------- main kernel ----------------

__global__ void __launch_bounds__(THREADS, 2)
linker_hmma_kernel(const float* __restrict__ node,
                   const int* __restrict__ src, const int* __restrict__ dst,
                   const float* __restrict__ b1v, const float* __restrict__ b2v,
                   const float* __restrict__ W3, const float* __restrict__ b3,
                   float* __restrict__ out, int E)
{
    extern __shared__ unsigned char smem[];
    const uint32_t sb = smem_u32(smem);
    const int tid = threadIdx.x;
    const int lid = tid & 31;
    const int wid = tid >> 5;
    const int wm  = wid & 1;        // M-warp: rows 32*wm .. +31 (2 x 16-row tiles)
    const int wn  = wid >> 1;       // N-warp 0..3
    const int e0  = blockIdx.x * MTILE;

    // ---- edge indices ----
    int* s_idx = (int*)(smem + IDX_OFF);
    if (tid < 128) {
        int e = e0 + (tid & 63);
        int v = 0;
        if (e < E) v = (tid < 64) ? __ldg(src + e) : __ldg(dst + e);
        s_idx[tid] = v;
    }
    __syncthreads();

    // ---- fire cp.async P-prefetch FIRST (lands by epilogue-1) ----
    #pragma unroll
    for (int it = 0; it < 8; it++) {
        int lin = it * THREADS + tid;
        int m  = lin >> 5;          // edge row 0..63
        int ch = lin & 31;          // 16B chunk within 512B row
        cp16(sb + P0S + m * RS_P + ch * 16,
             (const unsigned char*)g_P0 + (size_t)s_idx[m] * 512 + ch * 16);
        cp16(sb + P1S + m * RS_P + ch * 16,
             (const unsigned char*)g_P1 + (size_t)s_idx[64 + m] * 512 + ch * 16);
    }
    cp_commit();

    // ---- gather h_i/h_j (fp32) -> |diff| and prod tiles (single fp16) ----
    #pragma unroll
    for (int it = 0; it < 8; it++) {
        int lin = it * THREADS + tid;
        int m = lin >> 5, q = lin & 31;
        int rs = s_idx[m], rd = s_idx[64 + m];
        float4 vi = __ldg((const float4*)node + (size_t)rs * 32 + q);
        float4 vj = __ldg((const float4*)node + (size_t)rd * 32 + q);
        uint32_t off = m * RS_A + q * 8;
        *(uint2*)(smem + S0H + off) = make_uint2(
            pack_h2(fabsf(vi.x - vj.x), fabsf(vi.y - vj.y)),
            pack_h2(fabsf(vi.z - vj.z), fabsf(vi.w - vj.w)));
        *(uint2*)(smem + S1H + off) = make_uint2(
            pack_h2(vi.x * vj.x, vi.y * vj.y),
            pack_h2(vi.z * vj.z, vi.w * vj.w));
    }
    __syncthreads();

    // ======== layer 1 (nonlinear segs, plain fp16, 2Mx4N) ========
    float acc[2][8][4];
    #pragma unroll
    for (int mt = 0; mt < 2; mt++)
        #pragma unroll
        for (int np = 0; np < 8; np++)
            #pragma unroll
            for (int j = 0; j < 4; j++) acc[mt][np][j] = 0.f;

    #pragma unroll 1
    for (int sg = 0; sg < 2; sg++) {
        const uint32_t abase = sg ? S1H : S0H;
        #pragma unroll 1
        for (int ks = 0; ks < 8; ks++) {
            uint32_t ah[2][4];
            #pragma unroll
            for (int mt = 0; mt < 2; mt++) {
                uint32_t ab = sb + abase
                            + (wm * 32 + mt * 16 + (lid & 15)) * RS_A
                            + ks * 32 + ((lid >> 4) << 4);
                ldsm4(ah[mt], ab);
            }
            // site = ((sg*8+ks)*2 + wn>>1)*16 + (wn&1)*8 + np, 256B each
            const unsigned char* bp =
                g_w1h + ((size_t)(((sg << 3) + ks) * 2 + (wn >> 1)) << 12)
                      + ((size_t)(wn & 1) << 11) + (lid << 3);
            #pragma unroll
            for (int np = 0; np < 8; np++) {
                uint2 b = __ldg((const uint2*)(bp + np * 256));
                hmma_h(acc[0][np], ah[0], b);
                hmma_h(acc[1][np], ah[1], b);
            }
        }
    }
    cp_wait_all();     // P staging landed (this thread's copies)
    __syncthreads();   // everyone's copies + all ldsm of S done (X overwrites)

    // ---- epilogue 1: + (P0s+P1s) + b1, relu, fp16, store x1 ----
    {
        #pragma unroll
        for (int mt = 0; mt < 2; mt++) {
            int rr = wm * 32 + mt * 16 + (lid >> 2);
            #pragma unroll
            for (int np = 0; np < 8; np++) {
                int c = wn * 64 + np * 8 + (lid & 3) * 2;
                float2 bb = __ldg((const float2*)(b1v + c));
                uint32_t pa = hadd2u(*(uint32_t*)(smem + P0S + rr * RS_P + c * 2),
                                     *(uint32_t*)(smem + P1S + rr * RS_P + c * 2));
                uint32_t pb = hadd2u(*(uint32_t*)(smem + P0S + (rr + 8) * RS_P + c * 2),
                                     *(uint32_t*)(smem + P1S + (rr + 8) * RS_P + c * 2));
                float2 qa = __half22float2(*reinterpret_cast<__half2*>(&pa));
                float2 qb = __half22float2(*reinterpret_cast<__half2*>(&pb));
                *(uint32_t*)(smem + X_OFF + rr * RS_X + c * 2) =
                    pack_h2(fmaxf(acc[mt][np][0] + bb.x + qa.x, 0.f),
                            fmaxf(acc[mt][np][1] + bb.y + qa.y, 0.f));
                *(uint32_t*)(smem + X_OFF + (rr + 8) * RS_X + c * 2) =
                    pack_h2(fmaxf(acc[mt][np][2] + bb.x + qb.x, 0.f),
                            fmaxf(acc[mt][np][3] + bb.y + qb.y, 0.f));
            }
        }
    }
    __syncthreads();

    // ======== layer 2 (plain fp16, 2Mx4N) ========
    float acc2[2][4][4];
    #pragma unroll
    for (int mt = 0; mt < 2; mt++)
        #pragma unroll
        for (int np = 0; np < 4; np++)
            #pragma unroll
            for (int j = 0; j < 4; j++) acc2[mt][np][j] = 0.f;

    #pragma unroll 1
    for (int ks = 0; ks < 16; ks++) {
        uint32_t ah[2][4];
        #pragma unroll
        for (int mt = 0; mt < 2; mt++) {
            uint32_t ab = sb + X_OFF
                        + (wm * 32 + mt * 16 + (lid & 15)) * RS_X
                        + ks * 32 + ((lid >> 4) << 4);
            ldsm4(ah[mt], ab);
        }
        // site = (ks*2 + wn>>1)*8 + (wn&1)*4 + np, 256B each
        const unsigned char* bp =
            g_w2h + ((size_t)(ks * 2 + (wn >> 1)) << 11)
                  + ((size_t)(wn & 1) << 10) + (lid << 3);
        #pragma unroll
        for (int np = 0; np < 4; np++) {
            uint2 b = __ldg((const uint2*)(bp + np * 256));
            hmma_h(acc2[0][np], ah[0], b);
            hmma_h(acc2[1][np], ah[1], b);
        }
    }
    __syncthreads();   // X reads done before sred overwrites region

    // ---- epilogue 2: relu(+b2), @W3, reduce, +b3 ----
    float* sred = (float*)smem;    // [4 wn][64 rows][2 outs]
    {
        #pragma unroll
        for (int mt = 0; mt < 2; mt++) {
            int rr = wm * 32 + mt * 16 + (lid >> 2);
            float s00 = 0.f, s01 = 0.f, s10 = 0.f, s11 = 0.f;
            #pragma unroll
            for (int np = 0; np < 4; np++) {
                int c = wn * 32 + np * 8 + (lid & 3) * 2;
                float bb0 = __ldg(b2v + c), bb1 = __ldg(b2v + c + 1);
                float x0 = fmaxf(acc2[mt][np][0] + bb0, 0.f);
                float x1 = fmaxf(acc2[mt][np][1] + bb1, 0.f);
                float x2 = fmaxf(acc2[mt][np][2] + bb0, 0.f);
                float x3 = fmaxf(acc2[mt][np][3] + bb1, 0.f);
                float w00 = __ldg(W3 + c * 2),       w01 = __ldg(W3 + c * 2 + 1);
                float w10 = __ldg(W3 + (c + 1) * 2), w11 = __ldg(W3 + (c + 1) * 2 + 1);
                s00 += x0 * w00 + x1 * w10;
                s01 += x0 * w01 + x1 * w11;
                s10 += x2 * w00 + x3 * w10;
                s11 += x2 * w01 + x3 * w11;
            }
            s00 += __shfl_xor_sync(0xffffffffu, s00, 1);
            s00 += __shfl_xor_sync(0xffffffffu, s00, 2);
            s01 += __shfl_xor_sync(0xffffffffu, s01, 1);
            s01 += __shfl_xor_sync(0xffffffffu, s01, 2);
            s10 += __shfl_xor_sync(0xffffffffu, s10, 1);
            s10 += __shfl_xor_sync(0xffffffffu, s10, 2);
            s11 += __shfl_xor_sync(0xffffffffu, s11, 1);
            s11 += __shfl_xor_sync(0xffffffffu, s11, 2);
            if ((lid & 3) == 0) {
                sred[(wn * 64 + rr) * 2 + 0] = s00;
                sred[(wn * 64 + rr) * 2 + 1] = s01;
                sred[(wn * 64 + rr + 8) * 2 + 0] = s10;
                sred[(wn * 64 + rr + 8) * 2 + 1] = s11;
            }
        }
    }
    __syncthreads();

    if (tid < 64) {
        int e = e0 + tid;
        if (e < E) {
            float o0 = sred[tid * 2 + 0] + sred[(64 + tid) * 2 + 0]
                     + sred[(128 + tid) * 2 + 0] + sred[(192 + tid) * 2 + 0];
            float o1 = sred[tid * 2 + 1] + sred[(64 + tid) * 2 + 1]
                     + sred[(128 + tid) * 2 + 1] + sred[(192 + tid) * 2 + 1];
            out[2 * e + 0] = o0 + __ldg(b3 + 0);
            out[2 * e + 1] = o1 + __ldg(b3 + 1);
        }
    }
}

extern "C" void kernel_launch(void* const* d_in, const int* in_sizes, int n_in,
                              void* d_out, int out_size)
{
    const float* node = (const float*)d_in[0];
    const int*   src  = (const int*)  d_in[1];
    const int*   dst  = (const int*)  d_in[2];
    const float* W1   = (const float*)d_in[3];
    const float* b1   = (const float*)d_in[4];
    const float* W2   = (const float*)d_in[5];
    const float* b2   = (const float*)d_in[6];
    const float* W3   = (const float*)d_in[7];
    const float* b3   = (const float*)d_in[8];
    float* out = (float*)d_out;

    const int E  = in_sizes[1];
    int nn = in_sizes[0] / 128;
    if (nn > MAXN) nn = MAXN;

    prep_weights<<<448, 256>>>(W1, W2);

    cudaFuncSetAttribute(precompute_P_kernel,
                         cudaFuncAttributeMaxDynamicSharedMemorySize, SMEM_PRE);
    precompute_P_kernel<<<(nn + 127) / 128, 512, SMEM_PRE>>>(node, nn);

    cudaFuncSetAttribute(linker_hmma_kernel,
                         cudaFuncAttributeMaxDynamicSharedMemorySize, SMEM_BYTES);
    const int grid = (E + MTILE - 1) / MTILE;
    linker_hmma_kernel<<<grid, THREADS, SMEM_BYTES>>>(
        node, src, dst, b1, b2, W3, b3, out, E);
}